// round 5
// baseline (speedup 1.0000x reference)
#include <cuda_runtime.h>
#include <cuda_bf16.h>
#include <mma.h>
#include <math.h>
#include <cstdint>

using namespace nvcuda;

#define BSZ 4
#define SEQ 512
#define DM 1024
#define NH 16
#define NKV 4
#define HD 64
#define NROWS (BSZ*SEQ)          // 2048
#define OUT_ELEMS (BSZ*SEQ*DM)

// Scratch (device globals; no runtime allocation allowed)
__device__ float g_xq[NROWS * DM];                 // 8 MB
__device__ float g_xk[NROWS * (NKV*HD)];           // 2 MB
__device__ float g_xkT[BSZ * NKV * HD * SEQ];      // 2 MB
__device__ float g_ws[(size_t)64 * SEQ * DM];      // 134 MB ((b*16+h)*512+i)*1024 + c
__device__ float g_out_pre[NROWS * DM];            // 8 MB

// ===========================================================================
// Shared 64x64 WMMA tile core, bf16 3-term split (AhBh + AhBl + AlBh), fp32 acc
// 256 threads = 8 warps; warp (wm,wn) in 4x2; each warp: 16x32 C patch.
// A: [64 x K] row-major (lda), B: [K x 64] row-major (ldb), C: [64 x 64] (ldc)
// kceil must be a multiple of 16 and within valid memory for both operands.
// ===========================================================================
__device__ __forceinline__ void gemm64_core(const float* __restrict__ A, int lda,
                                            const float* __restrict__ B, int ldb,
                                            float* __restrict__ C, int ldc,
                                            int kceil) {
    __shared__ __nv_bfloat16 As_h[64 * 16], As_l[64 * 16];
    __shared__ __nv_bfloat16 Bs_h[16 * 64], Bs_l[16 * 64];

    int tid = threadIdx.x;
    int w = tid >> 5;
    int wm = w >> 1;          // 0..3
    int wn = w & 1;           // 0..1

    int arow = tid >> 2;              // 0..63
    int acol = (tid & 3) * 4;         // 0,4,8,12
    int brow = tid >> 4;              // 0..15
    int bcol = (tid & 15) * 4;        // 0..60

    wmma::fragment<wmma::accumulator, 16, 16, 16, float> acc[2];
    wmma::fill_fragment(acc[0], 0.0f);
    wmma::fill_fragment(acc[1], 0.0f);

    for (int k0 = 0; k0 < kceil; k0 += 16) {
        // Load + split A tile (64x16)
        float4 av = *(const float4*)&A[(size_t)arow * lda + k0 + acol];
        {
            float vv[4] = {av.x, av.y, av.z, av.w};
#pragma unroll
            for (int e = 0; e < 4; e++) {
                __nv_bfloat16 h = __float2bfloat16(vv[e]);
                As_h[arow * 16 + acol + e] = h;
                As_l[arow * 16 + acol + e] = __float2bfloat16(vv[e] - __bfloat162float(h));
            }
        }
        // Load + split B tile (16x64)
        float4 bv = *(const float4*)&B[(size_t)(k0 + brow) * ldb + bcol];
        {
            float vv[4] = {bv.x, bv.y, bv.z, bv.w};
#pragma unroll
            for (int e = 0; e < 4; e++) {
                __nv_bfloat16 h = __float2bfloat16(vv[e]);
                Bs_h[brow * 64 + bcol + e] = h;
                Bs_l[brow * 64 + bcol + e] = __float2bfloat16(vv[e] - __bfloat162float(h));
            }
        }
        __syncthreads();

        wmma::fragment<wmma::matrix_a, 16, 16, 16, __nv_bfloat16, wmma::row_major> ah, al;
        wmma::load_matrix_sync(ah, As_h + wm * 16 * 16, 16);
        wmma::load_matrix_sync(al, As_l + wm * 16 * 16, 16);
#pragma unroll
        for (int nf = 0; nf < 2; nf++) {
            wmma::fragment<wmma::matrix_b, 16, 16, 16, __nv_bfloat16, wmma::row_major> bh, bl;
            wmma::load_matrix_sync(bh, Bs_h + wn * 32 + nf * 16, 64);
            wmma::load_matrix_sync(bl, Bs_l + wn * 32 + nf * 16, 64);
            wmma::mma_sync(acc[nf], ah, bh, acc[nf]);
            wmma::mma_sync(acc[nf], ah, bl, acc[nf]);
            wmma::mma_sync(acc[nf], al, bh, acc[nf]);
        }
        __syncthreads();
    }

#pragma unroll
    for (int nf = 0; nf < 2; nf++)
        wmma::store_matrix_sync(C + (size_t)(wm * 16) * ldc + wn * 32 + nf * 16,
                                acc[nf], ldc, wmma::mem_row_major);
}

// ======================= Generic GEMM wrapper ==============================
// C[M,N] = A[M,K] @ B[K,N], all row-major, M%64==0, N%64==0, K%16==0
__global__ __launch_bounds__(256) void hgemm(const float* __restrict__ A,
                                             const float* __restrict__ B,
                                             float* __restrict__ C,
                                             int N, int K,
                                             int lda, int ldb, int ldc) {
    const float* Ab = A + (size_t)blockIdx.y * 64 * lda;
    const float* Bb = B + (size_t)blockIdx.x * 64;
    float* Cb = C + (size_t)blockIdx.y * 64 * ldc + (size_t)blockIdx.x * 64;
    gemm64_core(Ab, lda, Bb, ldb, Cb, ldc, K);
}

// ======================= ws GEMM: per-i batched ============================
// C_i[64 rows, 64 c] = attn_i[64, K=i+1] @ symbols[i][K, 64-slice]
// grid (16 c-tiles, 512 i). attn[j>i]==0 exactly -> Kceil rounding is free.
__global__ __launch_bounds__(256) void ws_gemm_w(const float* __restrict__ attn,
                                                 const float* __restrict__ symbols,
                                                 float* __restrict__ ws) {
    int i = blockIdx.y;
    int c0 = blockIdx.x * 64;
    int kceil = (i + 16) & ~15;   // ceil((i+1)/16)*16 <= 512
    const float* A = attn + (size_t)i * SEQ;                     // row stride SEQ*SEQ
    const float* B = symbols + (size_t)i * SEQ * DM + c0;        // row stride DM
    float* C = ws + (size_t)i * DM + c0;                         // row stride SEQ*DM
    gemm64_core(A, SEQ * SEQ, B, DM, C, SEQ * DM, kceil);
}

// ======================= wsv GEMM: out_pre = ws @ wv =======================
// grid (8 i-tiles, 64 rows=(b*16+h)); per block: C[64 i, 64 d], K=1024
__global__ __launch_bounds__(256) void wsv_gemm_w(const float* __restrict__ ws,
                                                  const float* __restrict__ wv,
                                                  float* __restrict__ outp) {
    int i0 = blockIdx.x * 64;
    int row = blockIdx.y;
    int b = row >> 4, h = row & 15, kv = h >> 2;
    const float* A = ws + ((size_t)row * SEQ + i0) * DM;         // lda = DM
    const float* B = wv + kv * HD;                               // ldb = NKV*HD
    float* C = outp + ((size_t)b * SEQ + i0) * DM + h * HD;      // ldc = DM
    gemm64_core(A, DM, B, NKV * HD, C, DM, DM);
}

// ======================= RoPE ==============================================
__global__ void rope_kernel(float* __restrict__ t,
                            const float* __restrict__ cs,
                            const float* __restrict__ sn,
                            int nheads, int total_pairs) {
    int idx = blockIdx.x * blockDim.x + threadIdx.x;
    if (idx >= total_pairs) return;
    int p = idx & 31;
    int h = (idx >> 5) % nheads;
    int row = idx / (32 * nheads);
    int pos = row & (SEQ - 1);
    float c = cs[pos * 32 + p];
    float s = sn[pos * 32 + p];
    float* base = t + ((size_t)row * nheads + h) * HD + 2 * p;
    float r = base[0], im = base[1];
    base[0] = r * c - im * s;
    base[1] = r * s + im * c;
}

// ======================= K transpose =======================================
__global__ void transpose_k(const float* __restrict__ xk, float* __restrict__ xkT) {
    int idx = blockIdx.x * blockDim.x + threadIdx.x;
    if (idx >= BSZ * NKV * HD * SEQ) return;
    int j = idx & 511;
    int d = (idx >> 9) & 63;
    int kv = (idx >> 15) & 3;
    int b = idx >> 17;
    xkT[idx] = xk[((size_t)(b * SEQ + j)) * (NKV * HD) + kv * HD + d];
}

// ======================= Scores + causal softmax ===========================
__global__ __launch_bounds__(256) void scores_softmax(const float* __restrict__ xq,
                                                      const float* __restrict__ xkT,
                                                      float* __restrict__ attn) {
    int i = blockIdx.x, h = blockIdx.y, b = blockIdx.z;
    int kv = h >> 2;
    int tid = threadIdx.x;
    __shared__ float qs[HD];
    __shared__ float red[256];
    if (tid < HD) qs[tid] = xq[((size_t)(b * SEQ + i)) * DM + h * HD + tid];
    __syncthreads();
    int nj = i + 1;
    const float* kT = xkT + ((size_t)(b * NKV + kv)) * HD * SEQ;
    float sc[2];
#pragma unroll
    for (int t = 0; t < 2; t++) {
        int j = tid + t * 256;
        float acc = -INFINITY;
        if (j < nj) {
            acc = 0.f;
#pragma unroll
            for (int d = 0; d < HD; d++) acc += qs[d] * kT[d * SEQ + j];
            acc *= 0.125f;
        }
        sc[t] = acc;
    }
    float m = fmaxf(sc[0], sc[1]);
    red[tid] = m;
    __syncthreads();
    for (int s2 = 128; s2 > 0; s2 >>= 1) {
        if (tid < s2) red[tid] = fmaxf(red[tid], red[tid + s2]);
        __syncthreads();
    }
    m = red[0];
    __syncthreads();
    float e[2];
#pragma unroll
    for (int t = 0; t < 2; t++) {
        int j = tid + t * 256;
        e[t] = (j < nj) ? expf(sc[t] - m) : 0.f;
    }
    red[tid] = e[0] + e[1];
    __syncthreads();
    for (int s2 = 128; s2 > 0; s2 >>= 1) {
        if (tid < s2) red[tid] += red[tid + s2];
        __syncthreads();
    }
    float inv = 1.0f / red[0];
    float* arow = attn + ((size_t)((b * NH + h) * SEQ + i)) * SEQ;
#pragma unroll
    for (int t = 0; t < 2; t++) {
        int j = tid + t * 256;
        arow[j] = e[t] * inv;
    }
}

// ===========================================================================
extern "C" void kernel_launch(void* const* d_in, const int* in_sizes, int n_in,
                              void* d_out, int out_size) {
    const float* x       = (const float*)d_in[0];
    const float* symbols = (const float*)d_in[1];
    const float* fcos    = (const float*)d_in[2];
    const float* fsin    = (const float*)d_in[3];
    const float* wq      = (const float*)d_in[4];
    const float* wk      = (const float*)d_in[5];
    const float* wv      = (const float*)d_in[6];
    const float* wo      = (const float*)d_in[7];

    float* out  = (float*)d_out;
    float* attn = out + OUT_ELEMS;

    float *p_xq, *p_xk, *p_xkT, *p_ws, *p_op;
    cudaGetSymbolAddress((void**)&p_xq, g_xq);
    cudaGetSymbolAddress((void**)&p_xk, g_xk);
    cudaGetSymbolAddress((void**)&p_xkT, g_xkT);
    cudaGetSymbolAddress((void**)&p_ws, g_ws);
    cudaGetSymbolAddress((void**)&p_op, g_out_pre);

    // 1) Q/K projections (WMMA bf16-split)
    hgemm<<<dim3(DM / 64, NROWS / 64), 256>>>(x, wq, p_xq, DM, DM, DM, DM, DM);
    hgemm<<<dim3((NKV * HD) / 64, NROWS / 64), 256>>>(x, wk, p_xk, NKV * HD, DM,
                                                      DM, NKV * HD, NKV * HD);

    // 2) RoPE
    int tp_q = NROWS * NH * 32;
    rope_kernel<<<(tp_q + 255) / 256, 256>>>(p_xq, fcos, fsin, NH, tp_q);
    int tp_k = NROWS * NKV * 32;
    rope_kernel<<<(tp_k + 255) / 256, 256>>>(p_xk, fcos, fsin, NKV, tp_k);

    // 3) K transpose
    transpose_k<<<(BSZ * NKV * HD * SEQ + 255) / 256, 256>>>(p_xk, p_xkT);

    // 4) Scores + causal softmax -> attn
    scores_softmax<<<dim3(SEQ, NH, BSZ), 256>>>(p_xq, p_xkT, attn);

    // 5) ws = attn @ symbols[i]  (WMMA, causal K)
    ws_gemm_w<<<dim3(DM / 64, SEQ), 256>>>(attn, symbols, p_ws);

    // 6) out_pre = ws @ wv  (WMMA)
    wsv_gemm_w<<<dim3(SEQ / 64, 64), 256>>>(p_ws, wv, p_op);

    // 7) out = out_pre @ wo (WMMA)
    hgemm<<<dim3(DM / 64, NROWS / 64), 256>>>(p_op, wo, out, DM, DM, DM, DM, DM);
}

// round 6
// speedup vs baseline: 2.9628x; 2.9628x over previous
#include <cuda_runtime.h>
#include <cuda_bf16.h>
#include <mma.h>
#include <math.h>
#include <cstdint>

using namespace nvcuda;

#define BSZ 4
#define SEQ 512
#define DM 1024
#define NH 16
#define NKV 4
#define HD 64
#define NROWS (BSZ*SEQ)          // 2048
#define OUT_ELEMS (BSZ*SEQ*DM)

// Scratch (device globals; no runtime allocation allowed)
__device__ float g_xq[NROWS * DM];                 // 8 MB
__device__ float g_xk[NROWS * (NKV*HD)];           // 2 MB
__device__ float g_xkT[BSZ * NKV * HD * SEQ];      // 2 MB
__device__ float g_ws[(size_t)64 * SEQ * DM];      // 134 MB ((b*16+h)*512+i)*1024 + c
__device__ float g_out_pre[NROWS * DM];            // 8 MB

// ===========================================================================
// bf16 hi/lo split store: writes (h0,h1),(h2,h3) and (l0..l3) as bfloat162
// off must be 4-element aligned.
// ===========================================================================
__device__ __forceinline__ void cvt_store4(__nv_bfloat16* __restrict__ H,
                                           __nv_bfloat16* __restrict__ L,
                                           int off, float4 v) {
    __nv_bfloat16 h0 = __float2bfloat16(v.x);
    __nv_bfloat16 h1 = __float2bfloat16(v.y);
    __nv_bfloat16 h2 = __float2bfloat16(v.z);
    __nv_bfloat16 h3 = __float2bfloat16(v.w);
    __nv_bfloat162 hh0; hh0.x = h0; hh0.y = h1;
    __nv_bfloat162 hh1; hh1.x = h2; hh1.y = h3;
    *(__nv_bfloat162*)(H + off)     = hh0;
    *(__nv_bfloat162*)(H + off + 2) = hh1;
    __nv_bfloat162 ll0, ll1;
    ll0.x = __float2bfloat16(v.x - __bfloat162float(h0));
    ll0.y = __float2bfloat16(v.y - __bfloat162float(h1));
    ll1.x = __float2bfloat16(v.z - __bfloat162float(h2));
    ll1.y = __float2bfloat16(v.w - __bfloat162float(h3));
    *(__nv_bfloat162*)(L + off)     = ll0;
    *(__nv_bfloat162*)(L + off + 2) = ll1;
}

// ===========================================================================
// Tiled WMMA GEMM core, bf16 3-term split (AhBh + AhBl + AlBh), fp32 acc.
// BM x BN block tile, BK=32, 256 threads = 8 warps of 32x32 warp tiles.
// Double-buffered smem, register-staged global prefetch, 1 sync per chunk.
// A: [BM x K] (lda), B: [K x BN] (ldb), C: [BM x BN] (ldc). kceil % 32 == 0.
// ===========================================================================
template<int BM, int BN>
__device__ __forceinline__ void gemm_core(const float* __restrict__ A, size_t lda,
                                          const float* __restrict__ B, size_t ldb,
                                          float* __restrict__ C, size_t ldc,
                                          int kceil) {
    constexpr int APAD = 40;            // 32 + 8 pad (multiple of 8)
    constexpr int BPAD = BN + 8;
    constexpr int ASZ  = BM * APAD;
    constexpr int BSZ_ = 32 * BPAD;
    constexpr int BUFSZ = 2 * ASZ + 2 * BSZ_;   // elems per buffer (Ah,Al,Bh,Bl)
    constexpr int N4A = BM / 32;        // float4 per thread for A tile
    constexpr int N4B = BN / 32;        // float4 per thread for B tile
    constexpr int WR = BM / 32;         // warp rows

    extern __shared__ char smraw[];
    __nv_bfloat16* smbase = (__nv_bfloat16*)smraw;

    int tid = threadIdx.x;
    int w = tid >> 5;
    int wm = w % WR;
    int wn = w / WR;

    wmma::fragment<wmma::accumulator, 16, 16, 16, float> acc[2][2];
#pragma unroll
    for (int mi = 0; mi < 2; mi++)
#pragma unroll
        for (int ni = 0; ni < 2; ni++) wmma::fill_fragment(acc[mi][ni], 0.0f);

    float4 ra[N4A], rb[N4B];

    // prologue: prefetch chunk 0
#pragma unroll
    for (int it = 0; it < N4A; it++) {
        int idx4 = tid + it * 256;
        int row = idx4 >> 3;
        int kc = (idx4 & 7) * 4;
        ra[it] = *(const float4*)&A[(size_t)row * lda + kc];
    }
#pragma unroll
    for (int it = 0; it < N4B; it++) {
        int idx4 = tid + it * 256;
        int row = idx4 / (BN / 4);
        int nc = (idx4 % (BN / 4)) * 4;
        rb[it] = *(const float4*)&B[(size_t)row * ldb + nc];
    }

    int nch = kceil >> 5;
    int cur = 0;
    for (int ch = 0; ch < nch; ch++) {
        __nv_bfloat16* Ah = smbase + cur * BUFSZ;
        __nv_bfloat16* Al = Ah + ASZ;
        __nv_bfloat16* Bh = Al + ASZ;
        __nv_bfloat16* Bl = Bh + BSZ_;

        // convert + store staged registers into smem buffer `cur`
#pragma unroll
        for (int it = 0; it < N4A; it++) {
            int idx4 = tid + it * 256;
            int row = idx4 >> 3;
            int kc = (idx4 & 7) * 4;
            cvt_store4(Ah, Al, row * APAD + kc, ra[it]);
        }
#pragma unroll
        for (int it = 0; it < N4B; it++) {
            int idx4 = tid + it * 256;
            int row = idx4 / (BN / 4);
            int nc = (idx4 % (BN / 4)) * 4;
            cvt_store4(Bh, Bl, row * BPAD + nc, rb[it]);
        }
        __syncthreads();

        // prefetch next chunk (overlaps with MMA below)
        if (ch + 1 < nch) {
            int k0 = (ch + 1) * 32;
#pragma unroll
            for (int it = 0; it < N4A; it++) {
                int idx4 = tid + it * 256;
                int row = idx4 >> 3;
                int kc = (idx4 & 7) * 4;
                ra[it] = *(const float4*)&A[(size_t)row * lda + k0 + kc];
            }
#pragma unroll
            for (int it = 0; it < N4B; it++) {
                int idx4 = tid + it * 256;
                int row = idx4 / (BN / 4);
                int nc = (idx4 % (BN / 4)) * 4;
                rb[it] = *(const float4*)&B[(size_t)(k0 + row) * ldb + nc];
            }
        }

        // compute from buffer `cur`
#pragma unroll
        for (int kk = 0; kk < 32; kk += 16) {
            wmma::fragment<wmma::matrix_a, 16, 16, 16, __nv_bfloat16, wmma::row_major> ah[2], al[2];
#pragma unroll
            for (int mi = 0; mi < 2; mi++) {
                int r0 = (wm * 32 + mi * 16) * APAD + kk;
                wmma::load_matrix_sync(ah[mi], Ah + r0, APAD);
                wmma::load_matrix_sync(al[mi], Al + r0, APAD);
            }
#pragma unroll
            for (int ni = 0; ni < 2; ni++) {
                wmma::fragment<wmma::matrix_b, 16, 16, 16, __nv_bfloat16, wmma::row_major> bh, bl;
                int c0 = kk * BPAD + wn * 32 + ni * 16;
                wmma::load_matrix_sync(bh, Bh + c0, BPAD);
                wmma::load_matrix_sync(bl, Bl + c0, BPAD);
#pragma unroll
                for (int mi = 0; mi < 2; mi++) {
                    wmma::mma_sync(acc[mi][ni], ah[mi], bh, acc[mi][ni]);
                    wmma::mma_sync(acc[mi][ni], ah[mi], bl, acc[mi][ni]);
                    wmma::mma_sync(acc[mi][ni], al[mi], bh, acc[mi][ni]);
                }
            }
        }
        cur ^= 1;
    }

#pragma unroll
    for (int mi = 0; mi < 2; mi++)
#pragma unroll
        for (int ni = 0; ni < 2; ni++)
            wmma::store_matrix_sync(C + (size_t)(wm * 32 + mi * 16) * ldc + wn * 32 + ni * 16,
                                    acc[mi][ni], ldc, wmma::mem_row_major);
}

// smem byte sizes for the two instantiations
#define SMEM_64_128 ((2*(64*40) + 2*(32*136)) * 2 * 2)    // 55296
#define SMEM_128_64 ((2*(128*40) + 2*(32*72)) * 2 * 2)    // 59392

// ======================= GEMM wrappers =====================================
// Projections / wo: tile 128x64
__global__ __launch_bounds__(256) void gemm_proj(const float* __restrict__ A,
                                                 const float* __restrict__ B,
                                                 float* __restrict__ C,
                                                 int K, int lda, int ldb, int ldc) {
    const float* Ab = A + (size_t)blockIdx.y * 128 * lda;
    const float* Bb = B + (size_t)blockIdx.x * 64;
    float* Cb = C + (size_t)blockIdx.y * 128 * ldc + (size_t)blockIdx.x * 64;
    gemm_core<128, 64>(Ab, lda, Bb, ldb, Cb, ldc, K);
}

// ws: per-i batched, tile 64x128; C_i[64 rows, 128 c] = attn_i[64,K] @ symbols[i][K,128]
__global__ __launch_bounds__(256) void gemm_ws(const float* __restrict__ attn,
                                               const float* __restrict__ symbols,
                                               float* __restrict__ ws) {
    int i = blockIdx.y;
    int c0 = blockIdx.x * 128;
    int kceil = (i + 32) & ~31;    // attn[j>i]==0 exactly -> rounding is free
    const float* A = attn + (size_t)i * SEQ;               // lda = SEQ*SEQ (row = b*16+h)
    const float* B = symbols + (size_t)i * SEQ * DM + c0;  // ldb = DM
    float* C = ws + (size_t)i * DM + c0;                   // ldc = SEQ*DM
    gemm_core<64, 128>(A, (size_t)SEQ * SEQ, B, DM, C, (size_t)SEQ * DM, kceil);
}

// wsv: out_pre tile 128x64 per (row=b*16+h, i-tile)
__global__ __launch_bounds__(256) void gemm_wsv(const float* __restrict__ ws,
                                                const float* __restrict__ wv,
                                                float* __restrict__ outp) {
    int i0 = blockIdx.x * 128;
    int row = blockIdx.y;
    int b = row >> 4, h = row & 15, kv = h >> 2;
    const float* A = ws + ((size_t)row * SEQ + i0) * DM;     // lda = DM
    const float* B = wv + kv * HD;                           // ldb = NKV*HD
    float* C = outp + ((size_t)b * SEQ + i0) * DM + h * HD;  // ldc = DM
    gemm_core<128, 64>(A, DM, B, NKV * HD, C, DM, DM);
}

// ======================= RoPE ==============================================
__global__ void rope_kernel(float* __restrict__ t,
                            const float* __restrict__ cs,
                            const float* __restrict__ sn,
                            int nheads, int total_pairs) {
    int idx = blockIdx.x * blockDim.x + threadIdx.x;
    if (idx >= total_pairs) return;
    int p = idx & 31;
    int h = (idx >> 5) % nheads;
    int row = idx / (32 * nheads);
    int pos = row & (SEQ - 1);
    float c = cs[pos * 32 + p];
    float s = sn[pos * 32 + p];
    float* base = t + ((size_t)row * nheads + h) * HD + 2 * p;
    float r = base[0], im = base[1];
    base[0] = r * c - im * s;
    base[1] = r * s + im * c;
}

// ======================= K transpose =======================================
__global__ void transpose_k(const float* __restrict__ xk, float* __restrict__ xkT) {
    int idx = blockIdx.x * blockDim.x + threadIdx.x;
    if (idx >= BSZ * NKV * HD * SEQ) return;
    int j = idx & 511;
    int d = (idx >> 9) & 63;
    int kv = (idx >> 15) & 3;
    int b = idx >> 17;
    xkT[idx] = xk[((size_t)(b * SEQ + j)) * (NKV * HD) + kv * HD + d];
}

// ======================= Scores + causal softmax ===========================
__global__ __launch_bounds__(256) void scores_softmax(const float* __restrict__ xq,
                                                      const float* __restrict__ xkT,
                                                      float* __restrict__ attn) {
    int i = blockIdx.x, h = blockIdx.y, b = blockIdx.z;
    int kv = h >> 2;
    int tid = threadIdx.x;
    __shared__ float qs[HD];
    __shared__ float red[256];
    if (tid < HD) qs[tid] = xq[((size_t)(b * SEQ + i)) * DM + h * HD + tid];
    __syncthreads();
    int nj = i + 1;
    const float* kT = xkT + ((size_t)(b * NKV + kv)) * HD * SEQ;
    float sc[2];
#pragma unroll
    for (int t = 0; t < 2; t++) {
        int j = tid + t * 256;
        float acc = -INFINITY;
        if (j < nj) {
            acc = 0.f;
#pragma unroll
            for (int d = 0; d < HD; d++) acc += qs[d] * kT[d * SEQ + j];
            acc *= 0.125f;
        }
        sc[t] = acc;
    }
    float m = fmaxf(sc[0], sc[1]);
    red[tid] = m;
    __syncthreads();
    for (int s2 = 128; s2 > 0; s2 >>= 1) {
        if (tid < s2) red[tid] = fmaxf(red[tid], red[tid + s2]);
        __syncthreads();
    }
    m = red[0];
    __syncthreads();
    float e[2];
#pragma unroll
    for (int t = 0; t < 2; t++) {
        int j = tid + t * 256;
        e[t] = (j < nj) ? expf(sc[t] - m) : 0.f;
    }
    red[tid] = e[0] + e[1];
    __syncthreads();
    for (int s2 = 128; s2 > 0; s2 >>= 1) {
        if (tid < s2) red[tid] += red[tid + s2];
        __syncthreads();
    }
    float inv = 1.0f / red[0];
    float* arow = attn + ((size_t)((b * NH + h) * SEQ + i)) * SEQ;
#pragma unroll
    for (int t = 0; t < 2; t++) {
        int j = tid + t * 256;
        arow[j] = e[t] * inv;
    }
}

// ===========================================================================
extern "C" void kernel_launch(void* const* d_in, const int* in_sizes, int n_in,
                              void* d_out, int out_size) {
    const float* x       = (const float*)d_in[0];
    const float* symbols = (const float*)d_in[1];
    const float* fcos    = (const float*)d_in[2];
    const float* fsin    = (const float*)d_in[3];
    const float* wq      = (const float*)d_in[4];
    const float* wk      = (const float*)d_in[5];
    const float* wv      = (const float*)d_in[6];
    const float* wo      = (const float*)d_in[7];

    float* out  = (float*)d_out;
    float* attn = out + OUT_ELEMS;

    float *p_xq, *p_xk, *p_xkT, *p_ws, *p_op;
    cudaGetSymbolAddress((void**)&p_xq, g_xq);
    cudaGetSymbolAddress((void**)&p_xk, g_xk);
    cudaGetSymbolAddress((void**)&p_xkT, g_xkT);
    cudaGetSymbolAddress((void**)&p_ws, g_ws);
    cudaGetSymbolAddress((void**)&p_op, g_out_pre);

    // raise dynamic smem limits (host-side attribute set; not a stream op)
    cudaFuncSetAttribute(gemm_proj, cudaFuncAttributeMaxDynamicSharedMemorySize, SMEM_128_64);
    cudaFuncSetAttribute(gemm_wsv,  cudaFuncAttributeMaxDynamicSharedMemorySize, SMEM_128_64);
    cudaFuncSetAttribute(gemm_ws,   cudaFuncAttributeMaxDynamicSharedMemorySize, SMEM_64_128);

    // 1) Q/K projections
    gemm_proj<<<dim3(DM / 64, NROWS / 128), 256, SMEM_128_64>>>(x, wq, p_xq, DM, DM, DM, DM);
    gemm_proj<<<dim3((NKV * HD) / 64, NROWS / 128), 256, SMEM_128_64>>>(x, wk, p_xk, DM, DM,
                                                                        NKV * HD, NKV * HD);

    // 2) RoPE
    int tp_q = NROWS * NH * 32;
    rope_kernel<<<(tp_q + 255) / 256, 256>>>(p_xq, fcos, fsin, NH, tp_q);
    int tp_k = NROWS * NKV * 32;
    rope_kernel<<<(tp_k + 255) / 256, 256>>>(p_xk, fcos, fsin, NKV, tp_k);

    // 3) K transpose
    transpose_k<<<(BSZ * NKV * HD * SEQ + 255) / 256, 256>>>(p_xk, p_xkT);

    // 4) Scores + causal softmax -> attn
    scores_softmax<<<dim3(SEQ, NH, BSZ), 256>>>(p_xq, p_xkT, attn);

    // 5) ws = attn @ symbols[i]  (causal K, symbols read once)
    gemm_ws<<<dim3(DM / 128, SEQ), 256, SMEM_64_128>>>(attn, symbols, p_ws);

    // 6) out_pre = ws @ wv
    gemm_wsv<<<dim3(SEQ / 128, 64), 256, SMEM_128_64>>>(p_ws, wv, p_op);

    // 7) out = out_pre @ wo
    gemm_proj<<<dim3(DM / 64, NROWS / 128), 256, SMEM_128_64>>>(p_op, wo, out, DM, DM, DM, DM);
}

// round 7
// speedup vs baseline: 3.0425x; 1.0269x over previous
#include <cuda_runtime.h>
#include <cuda_bf16.h>
#include <mma.h>
#include <math.h>
#include <cstdint>

using namespace nvcuda;

#define BSZ 4
#define SEQ 512
#define DM 1024
#define NH 16
#define NKV 4
#define HD 64
#define NROWS (BSZ*SEQ)          // 2048
#define OUT_ELEMS (BSZ*SEQ*DM)

typedef __nv_bfloat16 bf16;

// Scratch (device globals; no runtime allocation allowed)
__device__ float g_xq[NROWS * DM];                  // 8 MB
__device__ float g_xk[NROWS * (NKV*HD)];            // 2 MB
__device__ float g_xkT[BSZ * NKV * HD * SEQ];       // 2 MB
__device__ bf16 g_xh[NROWS * DM],  g_xl[NROWS * DM];            // 4 MB each
__device__ bf16 g_wqh[DM * DM],    g_wql[DM * DM];              // 2 MB each
__device__ bf16 g_wkh[DM * NKV*HD], g_wkl[DM * NKV*HD];         // 0.5 MB each
__device__ bf16 g_wvh[DM * NKV*HD], g_wvl[DM * NKV*HD];         // 0.5 MB each
__device__ bf16 g_woh[DM * DM],    g_wol[DM * DM];              // 2 MB each
__device__ bf16 g_ah[(size_t)64 * SEQ * SEQ], g_al[(size_t)64 * SEQ * SEQ];  // 33.5 MB each
__device__ bf16 g_wsh[(size_t)64 * SEQ * DM], g_wsl[(size_t)64 * SEQ * DM];  // 67 MB each
__device__ bf16 g_oph[NROWS * DM], g_opl[NROWS * DM];           // 4 MB each

// ===========================================================================
// split helpers
// ===========================================================================
__device__ __forceinline__ void split_write4(bf16* __restrict__ H, bf16* __restrict__ L,
                                             size_t off, float4 v) {
    bf16 h0 = __float2bfloat16(v.x);
    bf16 h1 = __float2bfloat16(v.y);
    bf16 h2 = __float2bfloat16(v.z);
    bf16 h3 = __float2bfloat16(v.w);
    __nv_bfloat162 hh0; hh0.x = h0; hh0.y = h1;
    __nv_bfloat162 hh1; hh1.x = h2; hh1.y = h3;
    *(__nv_bfloat162*)(H + off)     = hh0;
    *(__nv_bfloat162*)(H + off + 2) = hh1;
    __nv_bfloat162 ll0, ll1;
    ll0.x = __float2bfloat16(v.x - __bfloat162float(h0));
    ll0.y = __float2bfloat16(v.y - __bfloat162float(h1));
    ll1.x = __float2bfloat16(v.z - __bfloat162float(h2));
    ll1.y = __float2bfloat16(v.w - __bfloat162float(h3));
    *(__nv_bfloat162*)(L + off)     = ll0;
    *(__nv_bfloat162*)(L + off + 2) = ll1;
}

// prep: elementwise fp32 -> (hi, lo) bf16 arrays; n4 = elem_count/4
__global__ void prep_split(const float* __restrict__ src,
                           bf16* __restrict__ h, bf16* __restrict__ l, int n4) {
    int idx = blockIdx.x * blockDim.x + threadIdx.x;
    if (idx >= n4) return;
    float4 v = ((const float4*)src)[idx];
    split_write4(h, l, (size_t)idx * 4, v);
}

// ===========================================================================
// Tiled WMMA GEMM core, bf16 3-term split (AhBh + AhBl + AlBh), fp32 acc.
// BM x BN tile, BK=32, 256 threads = 8 warps of 32x32 warp tiles.
// PA/PB: operand comes pre-split as (h,l) bf16 arrays (pure copy to smem).
//        otherwise f32 with in-loop conversion.
// EPIB: write C as (h,l) bf16 via smem staging; else fp32 store_matrix.
// ===========================================================================
template<int BM, int BN, bool PA, bool PB, bool EPIB>
__device__ __forceinline__ void gemm_core2(
        const bf16* __restrict__ Ah_g, const bf16* __restrict__ Al_g,
        const float* __restrict__ Af_g, size_t lda,
        const bf16* __restrict__ Bh_g, const bf16* __restrict__ Bl_g,
        const float* __restrict__ Bf_g, size_t ldb,
        float* __restrict__ Cf, bf16* __restrict__ Ch, bf16* __restrict__ Cl,
        size_t ldc, int kceil) {
    constexpr int APAD = 40;
    constexpr int BPAD = BN + 8;
    constexpr int ASZ  = BM * APAD;
    constexpr int BSZ_ = 32 * BPAD;
    constexpr int BUFSZ = 2 * ASZ + 2 * BSZ_;
    constexpr int N8A = BM / 64;   // uint4 (8 bf16) per thread, pre-split path
    constexpr int N4A = BM / 32;   // float4 per thread, f32 path
    constexpr int N8B = BN / 64;
    constexpr int N4B = BN / 32;
    constexpr int WR = BM / 32;

    extern __shared__ char smraw[];
    bf16* smbase = (bf16*)smraw;

    int tid = threadIdx.x;
    int w = tid >> 5;
    int wm = w % WR;
    int wn = w / WR;

    wmma::fragment<wmma::accumulator, 16, 16, 16, float> acc[2][2];
#pragma unroll
    for (int mi = 0; mi < 2; mi++)
#pragma unroll
        for (int ni = 0; ni < 2; ni++) wmma::fill_fragment(acc[mi][ni], 0.0f);

    uint4 rah[PA ? N8A : 1], ral[PA ? N8A : 1];
    float4 raf[PA ? 1 : N4A];
    uint4 rbh[PB ? N8B : 1], rbl[PB ? N8B : 1];
    float4 rbf[PB ? 1 : N4B];

    // ---- prefetch chunk 0
    if constexpr (PA) {
#pragma unroll
        for (int it = 0; it < N8A; it++) {
            int idx8 = tid + it * 256;
            int row = idx8 >> 2, kc = (idx8 & 3) * 8;
            rah[it] = *(const uint4*)&Ah_g[(size_t)row * lda + kc];
            ral[it] = *(const uint4*)&Al_g[(size_t)row * lda + kc];
        }
    } else {
#pragma unroll
        for (int it = 0; it < N4A; it++) {
            int idx4 = tid + it * 256;
            int row = idx4 >> 3, kc = (idx4 & 7) * 4;
            raf[it] = *(const float4*)&Af_g[(size_t)row * lda + kc];
        }
    }
    if constexpr (PB) {
#pragma unroll
        for (int it = 0; it < N8B; it++) {
            int idx8 = tid + it * 256;
            int row = idx8 / (BN / 8), nc = (idx8 % (BN / 8)) * 8;
            rbh[it] = *(const uint4*)&Bh_g[(size_t)row * ldb + nc];
            rbl[it] = *(const uint4*)&Bl_g[(size_t)row * ldb + nc];
        }
    } else {
#pragma unroll
        for (int it = 0; it < N4B; it++) {
            int idx4 = tid + it * 256;
            int row = idx4 / (BN / 4), nc = (idx4 % (BN / 4)) * 4;
            rbf[it] = *(const float4*)&Bf_g[(size_t)row * ldb + nc];
        }
    }

    int nch = kceil >> 5;
    int cur = 0;
    for (int ch = 0; ch < nch; ch++) {
        bf16* Ah = smbase + cur * BUFSZ;
        bf16* Al = Ah + ASZ;
        bf16* Bh = Al + ASZ;
        bf16* Bl = Bh + BSZ_;

        // ---- store staged chunk into smem
        if constexpr (PA) {
#pragma unroll
            for (int it = 0; it < N8A; it++) {
                int idx8 = tid + it * 256;
                int row = idx8 >> 2, kc = (idx8 & 3) * 8;
                *(uint4*)&Ah[row * APAD + kc] = rah[it];
                *(uint4*)&Al[row * APAD + kc] = ral[it];
            }
        } else {
#pragma unroll
            for (int it = 0; it < N4A; it++) {
                int idx4 = tid + it * 256;
                int row = idx4 >> 3, kc = (idx4 & 7) * 4;
                split_write4(Ah, Al, row * APAD + kc, raf[it]);
            }
        }
        if constexpr (PB) {
#pragma unroll
            for (int it = 0; it < N8B; it++) {
                int idx8 = tid + it * 256;
                int row = idx8 / (BN / 8), nc = (idx8 % (BN / 8)) * 8;
                *(uint4*)&Bh[row * BPAD + nc] = rbh[it];
                *(uint4*)&Bl[row * BPAD + nc] = rbl[it];
            }
        } else {
#pragma unroll
            for (int it = 0; it < N4B; it++) {
                int idx4 = tid + it * 256;
                int row = idx4 / (BN / 4), nc = (idx4 % (BN / 4)) * 4;
                split_write4(Bh, Bl, row * BPAD + nc, rbf[it]);
            }
        }
        __syncthreads();

        // ---- prefetch next chunk (overlaps MMA)
        if (ch + 1 < nch) {
            int k0 = (ch + 1) * 32;
            if constexpr (PA) {
#pragma unroll
                for (int it = 0; it < N8A; it++) {
                    int idx8 = tid + it * 256;
                    int row = idx8 >> 2, kc = (idx8 & 3) * 8;
                    rah[it] = *(const uint4*)&Ah_g[(size_t)row * lda + k0 + kc];
                    ral[it] = *(const uint4*)&Al_g[(size_t)row * lda + k0 + kc];
                }
            } else {
#pragma unroll
                for (int it = 0; it < N4A; it++) {
                    int idx4 = tid + it * 256;
                    int row = idx4 >> 3, kc = (idx4 & 7) * 4;
                    raf[it] = *(const float4*)&Af_g[(size_t)row * lda + k0 + kc];
                }
            }
            if constexpr (PB) {
#pragma unroll
                for (int it = 0; it < N8B; it++) {
                    int idx8 = tid + it * 256;
                    int row = idx8 / (BN / 8), nc = (idx8 % (BN / 8)) * 8;
                    rbh[it] = *(const uint4*)&Bh_g[(size_t)(k0 + row) * ldb + nc];
                    rbl[it] = *(const uint4*)&Bl_g[(size_t)(k0 + row) * ldb + nc];
                }
            } else {
#pragma unroll
                for (int it = 0; it < N4B; it++) {
                    int idx4 = tid + it * 256;
                    int row = idx4 / (BN / 4), nc = (idx4 % (BN / 4)) * 4;
                    rbf[it] = *(const float4*)&Bf_g[(size_t)(k0 + row) * ldb + nc];
                }
            }
        }

        // ---- MMA from buffer `cur`
#pragma unroll
        for (int kk = 0; kk < 32; kk += 16) {
            wmma::fragment<wmma::matrix_a, 16, 16, 16, bf16, wmma::row_major> ah[2], al[2];
#pragma unroll
            for (int mi = 0; mi < 2; mi++) {
                int r0 = (wm * 32 + mi * 16) * APAD + kk;
                wmma::load_matrix_sync(ah[mi], Ah + r0, APAD);
                wmma::load_matrix_sync(al[mi], Al + r0, APAD);
            }
#pragma unroll
            for (int ni = 0; ni < 2; ni++) {
                wmma::fragment<wmma::matrix_b, 16, 16, 16, bf16, wmma::row_major> bh, bl;
                int c0 = kk * BPAD + wn * 32 + ni * 16;
                wmma::load_matrix_sync(bh, Bh + c0, BPAD);
                wmma::load_matrix_sync(bl, Bl + c0, BPAD);
#pragma unroll
                for (int mi = 0; mi < 2; mi++) {
                    wmma::mma_sync(acc[mi][ni], ah[mi], bh, acc[mi][ni]);
                    wmma::mma_sync(acc[mi][ni], ah[mi], bl, acc[mi][ni]);
                    wmma::mma_sync(acc[mi][ni], al[mi], bh, acc[mi][ni]);
                }
            }
        }
        cur ^= 1;
    }

    // ---- epilogue
    if constexpr (!EPIB) {
#pragma unroll
        for (int mi = 0; mi < 2; mi++)
#pragma unroll
            for (int ni = 0; ni < 2; ni++)
                wmma::store_matrix_sync(Cf + (size_t)(wm * 32 + mi * 16) * ldc + wn * 32 + ni * 16,
                                        acc[mi][ni], ldc, wmma::mem_row_major);
    } else {
        __syncthreads();
        float* stg = (float*)smraw;
#pragma unroll
        for (int mi = 0; mi < 2; mi++)
#pragma unroll
            for (int ni = 0; ni < 2; ni++)
                wmma::store_matrix_sync(stg + (size_t)(wm * 32 + mi * 16) * BN + wn * 32 + ni * 16,
                                        acc[mi][ni], BN, wmma::mem_row_major);
        __syncthreads();
        constexpr int NE4 = BM * BN / 1024;
#pragma unroll
        for (int it = 0; it < NE4; it++) {
            int idx4 = tid + it * 256;
            int row = idx4 / (BN / 4), c = (idx4 % (BN / 4)) * 4;
            float4 v = *(const float4*)&stg[row * BN + c];
            split_write4(Ch, Cl, (size_t)row * ldc + c, v);
        }
    }
}

// smem byte sizes
#define SM_PROJ ((2*(128*40) + 2*(32*72)) * 2 * 2)   // 59392 (staging 32768 fits)
#define SM_WS   ((2*(64*40)  + 2*(32*136)) * 2 * 2)  // 55296 (staging 32768 fits)

// ======================= GEMM wrappers =====================================
// proj / wo: A,B pre-split, C fp32; tile 128x64
__global__ __launch_bounds__(256) void gemm_proj(const bf16* __restrict__ Ah,
                                                 const bf16* __restrict__ Al,
                                                 const bf16* __restrict__ Bh,
                                                 const bf16* __restrict__ Bl,
                                                 float* __restrict__ C,
                                                 int K, int lda, int ldb, int ldc) {
    size_t ao = (size_t)blockIdx.y * 128 * lda;
    size_t bo = (size_t)blockIdx.x * 64;
    float* Cb = C + (size_t)blockIdx.y * 128 * ldc + (size_t)blockIdx.x * 64;
    gemm_core2<128, 64, true, true, false>(Ah + ao, Al + ao, nullptr, lda,
                                           Bh + bo, Bl + bo, nullptr, ldb,
                                           Cb, nullptr, nullptr, ldc, K);
}

// ws: A=attn pre-split, B=symbols f32, C bf16 pair; tile 64x128, per-i batched
__global__ __launch_bounds__(256) void gemm_ws(const bf16* __restrict__ ah,
                                               const bf16* __restrict__ al,
                                               const float* __restrict__ symbols,
                                               bf16* __restrict__ wsh,
                                               bf16* __restrict__ wsl) {
    int i = blockIdx.y;
    int c0 = blockIdx.x * 128;
    int kceil = (i + 32) & ~31;              // attn[j>i]==0 exactly
    size_t ao = (size_t)i * SEQ;
    const float* B = symbols + (size_t)i * SEQ * DM + c0;
    size_t co = (size_t)i * DM + c0;
    gemm_core2<64, 128, true, false, true>(ah + ao, al + ao, nullptr, (size_t)SEQ * SEQ,
                                           nullptr, nullptr, B, DM,
                                           nullptr, wsh + co, wsl + co, (size_t)SEQ * DM, kceil);
}

// wsv: A=ws pre-split, B=wv pre-split, C bf16 pair; tile 128x64
__global__ __launch_bounds__(256) void gemm_wsv(const bf16* __restrict__ wsh,
                                                const bf16* __restrict__ wsl,
                                                const bf16* __restrict__ wvh,
                                                const bf16* __restrict__ wvl,
                                                bf16* __restrict__ oph,
                                                bf16* __restrict__ opl) {
    int i0 = blockIdx.x * 128;
    int row = blockIdx.y;
    int b = row >> 4, h = row & 15, kv = h >> 2;
    size_t ao = ((size_t)row * SEQ + i0) * DM;
    size_t bo = (size_t)kv * HD;
    size_t co = ((size_t)b * SEQ + i0) * DM + h * HD;
    gemm_core2<128, 64, true, true, true>(wsh + ao, wsl + ao, nullptr, DM,
                                          wvh + bo, wvl + bo, nullptr, NKV * HD,
                                          nullptr, oph + co, opl + co, DM, DM);
}

// ======================= RoPE ==============================================
__global__ void rope_kernel(float* __restrict__ t,
                            const float* __restrict__ cs,
                            const float* __restrict__ sn,
                            int nheads, int total_pairs) {
    int idx = blockIdx.x * blockDim.x + threadIdx.x;
    if (idx >= total_pairs) return;
    int p = idx & 31;
    int h = (idx >> 5) % nheads;
    int row = idx / (32 * nheads);
    int pos = row & (SEQ - 1);
    float c = cs[pos * 32 + p];
    float s = sn[pos * 32 + p];
    float* base = t + ((size_t)row * nheads + h) * HD + 2 * p;
    float r = base[0], im = base[1];
    base[0] = r * c - im * s;
    base[1] = r * s + im * c;
}

// ======================= K transpose =======================================
__global__ void transpose_k(const float* __restrict__ xk, float* __restrict__ xkT) {
    int idx = blockIdx.x * blockDim.x + threadIdx.x;
    if (idx >= BSZ * NKV * HD * SEQ) return;
    int j = idx & 511;
    int d = (idx >> 9) & 63;
    int kv = (idx >> 15) & 3;
    int b = idx >> 17;
    xkT[idx] = xk[((size_t)(b * SEQ + j)) * (NKV * HD) + kv * HD + d];
}

// ======================= Scores + causal softmax (+ split write) ===========
__global__ __launch_bounds__(256) void scores_softmax(const float* __restrict__ xq,
                                                      const float* __restrict__ xkT,
                                                      float* __restrict__ attn,
                                                      bf16* __restrict__ ah_g,
                                                      bf16* __restrict__ al_g) {
    int i = blockIdx.x, h = blockIdx.y, b = blockIdx.z;
    int kv = h >> 2;
    int tid = threadIdx.x;
    __shared__ float qs[HD];
    __shared__ float red[256];
    if (tid < HD) qs[tid] = xq[((size_t)(b * SEQ + i)) * DM + h * HD + tid];
    __syncthreads();
    int nj = i + 1;
    const float* kT = xkT + ((size_t)(b * NKV + kv)) * HD * SEQ;
    float sc[2];
#pragma unroll
    for (int t = 0; t < 2; t++) {
        int j = tid + t * 256;
        float acc = -INFINITY;
        if (j < nj) {
            acc = 0.f;
#pragma unroll
            for (int d = 0; d < HD; d++) acc += qs[d] * kT[d * SEQ + j];
            acc *= 0.125f;
        }
        sc[t] = acc;
    }
    float m = fmaxf(sc[0], sc[1]);
    red[tid] = m;
    __syncthreads();
    for (int s2 = 128; s2 > 0; s2 >>= 1) {
        if (tid < s2) red[tid] = fmaxf(red[tid], red[tid + s2]);
        __syncthreads();
    }
    m = red[0];
    __syncthreads();
    float e[2];
#pragma unroll
    for (int t = 0; t < 2; t++) {
        int j = tid + t * 256;
        e[t] = (j < nj) ? expf(sc[t] - m) : 0.f;
    }
    red[tid] = e[0] + e[1];
    __syncthreads();
    for (int s2 = 128; s2 > 0; s2 >>= 1) {
        if (tid < s2) red[tid] += red[tid + s2];
        __syncthreads();
    }
    float inv = 1.0f / red[0];
    size_t base = ((size_t)((b * NH + h) * SEQ + i)) * SEQ;
#pragma unroll
    for (int t = 0; t < 2; t++) {
        int j = tid + t * 256;
        float a = e[t] * inv;
        attn[base + j] = a;
        bf16 hh = __float2bfloat16(a);
        ah_g[base + j] = hh;
        al_g[base + j] = __float2bfloat16(a - __bfloat162float(hh));
    }
}

// ===========================================================================
extern "C" void kernel_launch(void* const* d_in, const int* in_sizes, int n_in,
                              void* d_out, int out_size) {
    const float* x       = (const float*)d_in[0];
    const float* symbols = (const float*)d_in[1];
    const float* fcos    = (const float*)d_in[2];
    const float* fsin    = (const float*)d_in[3];
    const float* wq      = (const float*)d_in[4];
    const float* wk      = (const float*)d_in[5];
    const float* wv      = (const float*)d_in[6];
    const float* wo      = (const float*)d_in[7];

    float* out  = (float*)d_out;
    float* attn = out + OUT_ELEMS;

    float *p_xq, *p_xk, *p_xkT;
    bf16 *p_xh, *p_xl, *p_wqh, *p_wql, *p_wkh, *p_wkl, *p_wvh, *p_wvl, *p_woh, *p_wol;
    bf16 *p_ah, *p_al, *p_wsh, *p_wsl, *p_oph, *p_opl;
    cudaGetSymbolAddress((void**)&p_xq, g_xq);
    cudaGetSymbolAddress((void**)&p_xk, g_xk);
    cudaGetSymbolAddress((void**)&p_xkT, g_xkT);
    cudaGetSymbolAddress((void**)&p_xh, g_xh);   cudaGetSymbolAddress((void**)&p_xl, g_xl);
    cudaGetSymbolAddress((void**)&p_wqh, g_wqh); cudaGetSymbolAddress((void**)&p_wql, g_wql);
    cudaGetSymbolAddress((void**)&p_wkh, g_wkh); cudaGetSymbolAddress((void**)&p_wkl, g_wkl);
    cudaGetSymbolAddress((void**)&p_wvh, g_wvh); cudaGetSymbolAddress((void**)&p_wvl, g_wvl);
    cudaGetSymbolAddress((void**)&p_woh, g_woh); cudaGetSymbolAddress((void**)&p_wol, g_wol);
    cudaGetSymbolAddress((void**)&p_ah, g_ah);   cudaGetSymbolAddress((void**)&p_al, g_al);
    cudaGetSymbolAddress((void**)&p_wsh, g_wsh); cudaGetSymbolAddress((void**)&p_wsl, g_wsl);
    cudaGetSymbolAddress((void**)&p_oph, g_oph); cudaGetSymbolAddress((void**)&p_opl, g_opl);

    cudaFuncSetAttribute(gemm_proj, cudaFuncAttributeMaxDynamicSharedMemorySize, SM_PROJ);
    cudaFuncSetAttribute(gemm_wsv,  cudaFuncAttributeMaxDynamicSharedMemorySize, SM_PROJ);
    cudaFuncSetAttribute(gemm_ws,   cudaFuncAttributeMaxDynamicSharedMemorySize, SM_WS);

    // 0) pre-split x and weights (one-time conversions)
    prep_split<<<(NROWS * DM / 4 + 255) / 256, 256>>>(x, p_xh, p_xl, NROWS * DM / 4);
    prep_split<<<(DM * DM / 4 + 255) / 256, 256>>>(wq, p_wqh, p_wql, DM * DM / 4);
    prep_split<<<(DM * NKV * HD / 4 + 255) / 256, 256>>>(wk, p_wkh, p_wkl, DM * NKV * HD / 4);
    prep_split<<<(DM * NKV * HD / 4 + 255) / 256, 256>>>(wv, p_wvh, p_wvl, DM * NKV * HD / 4);
    prep_split<<<(DM * DM / 4 + 255) / 256, 256>>>(wo, p_woh, p_wol, DM * DM / 4);

    // 1) Q/K projections (pre-split operands, fp32 out)
    gemm_proj<<<dim3(DM / 64, NROWS / 128), 256, SM_PROJ>>>(p_xh, p_xl, p_wqh, p_wql,
                                                            p_xq, DM, DM, DM, DM);
    gemm_proj<<<dim3((NKV * HD) / 64, NROWS / 128), 256, SM_PROJ>>>(p_xh, p_xl, p_wkh, p_wkl,
                                                                    p_xk, DM, DM, NKV * HD, NKV * HD);

    // 2) RoPE
    int tp_q = NROWS * NH * 32;
    rope_kernel<<<(tp_q + 255) / 256, 256>>>(p_xq, fcos, fsin, NH, tp_q);
    int tp_k = NROWS * NKV * 32;
    rope_kernel<<<(tp_k + 255) / 256, 256>>>(p_xk, fcos, fsin, NKV, tp_k);

    // 3) K transpose
    transpose_k<<<(BSZ * NKV * HD * SEQ + 255) / 256, 256>>>(p_xk, p_xkT);

    // 4) Scores + causal softmax -> attn fp32 (output) + bf16 hi/lo split
    scores_softmax<<<dim3(SEQ, NH, BSZ), 256>>>(p_xq, p_xkT, attn, p_ah, p_al);

    // 5) ws = attn @ symbols[i]  (causal K, symbols read once, ws stored bf16 hi/lo)
    gemm_ws<<<dim3(DM / 128, SEQ), 256, SM_WS>>>(p_ah, p_al, symbols, p_wsh, p_wsl);

    // 6) out_pre = ws @ wv (bf16 hi/lo out)
    gemm_wsv<<<dim3(SEQ / 128, 64), 256, SM_PROJ>>>(p_wsh, p_wsl, p_wvh, p_wvl, p_oph, p_opl);

    // 7) out = out_pre @ wo (fp32 out)
    gemm_proj<<<dim3(DM / 64, NROWS / 128), 256, SM_PROJ>>>(p_oph, p_opl, p_woh, p_wol,
                                                            out, DM, DM, DM, DM);
}

// round 8
// speedup vs baseline: 3.4573x; 1.1364x over previous
#include <cuda_runtime.h>
#include <cuda_bf16.h>
#include <mma.h>
#include <math.h>
#include <cstdint>

using namespace nvcuda;

#define BSZ 4
#define SEQ 512
#define DM 1024
#define NH 16
#define NKV 4
#define HD 64
#define NROWS (BSZ*SEQ)          // 2048
#define OUT_ELEMS (BSZ*SEQ*DM)

typedef __nv_bfloat16 bf16;

// Scratch (device globals; no runtime allocation allowed)
__device__ float g_xq[NROWS * DM];                  // 8 MB (post-rope)
__device__ float g_xk[NROWS * (NKV*HD)];            // 2 MB (post-rope)
__device__ float g_xkT[BSZ * NKV * HD * SEQ];       // 2 MB
__device__ bf16 g_xh[NROWS * DM],  g_xl[NROWS * DM];
__device__ bf16 g_wqh[DM * DM],    g_wql[DM * DM];
__device__ bf16 g_wkh[DM * NKV*HD], g_wkl[DM * NKV*HD];
__device__ bf16 g_wvh[DM * NKV*HD], g_wvl[DM * NKV*HD];
__device__ bf16 g_woh[DM * DM],    g_wol[DM * DM];
__device__ bf16 g_ah[(size_t)64 * SEQ * SEQ], g_al[(size_t)64 * SEQ * SEQ];
__device__ bf16 g_wsh[(size_t)64 * SEQ * DM], g_wsl[(size_t)64 * SEQ * DM];
__device__ bf16 g_oph[NROWS * DM], g_opl[NROWS * DM];

// ===========================================================================
// split helpers
// ===========================================================================
__device__ __forceinline__ void split_write4(bf16* __restrict__ H, bf16* __restrict__ L,
                                             size_t off, float4 v) {
    bf16 h0 = __float2bfloat16(v.x);
    bf16 h1 = __float2bfloat16(v.y);
    bf16 h2 = __float2bfloat16(v.z);
    bf16 h3 = __float2bfloat16(v.w);
    __nv_bfloat162 hh0; hh0.x = h0; hh0.y = h1;
    __nv_bfloat162 hh1; hh1.x = h2; hh1.y = h3;
    *(__nv_bfloat162*)(H + off)     = hh0;
    *(__nv_bfloat162*)(H + off + 2) = hh1;
    __nv_bfloat162 ll0, ll1;
    ll0.x = __float2bfloat16(v.x - __bfloat162float(h0));
    ll0.y = __float2bfloat16(v.y - __bfloat162float(h1));
    ll1.x = __float2bfloat16(v.z - __bfloat162float(h2));
    ll1.y = __float2bfloat16(v.w - __bfloat162float(h3));
    *(__nv_bfloat162*)(L + off)     = ll0;
    *(__nv_bfloat162*)(L + off + 2) = ll1;
}

__global__ void prep_split(const float* __restrict__ src,
                           bf16* __restrict__ h, bf16* __restrict__ l, int n4) {
    int idx = blockIdx.x * blockDim.x + threadIdx.x;
    if (idx >= n4) return;
    float4 v = ((const float4*)src)[idx];
    split_write4(h, l, (size_t)idx * 4, v);
}

// ===========================================================================
// Generalized WMMA GEMM core. 3-term bf16 split (AhBh + AhBl + AlBh), fp32 acc.
// 8 warps, warp tile 32 x WNW; CTA tile BM x BN; BK=32 double-buffered.
// PA/PB: operand pre-split (h,l) bf16 (pure smem copy). Else f32 + in-loop cvt.
// EPI: 0 = fp32 out, 1 = bf16 (h,l) out, 2 = fp32 out with fused RoPE.
// ===========================================================================
template<int BM, int BN, int WNW, bool PA, bool PB, int EPI>
__device__ __forceinline__ void gcore(
        const bf16* __restrict__ Ah_g, const bf16* __restrict__ Al_g,
        const float* __restrict__ Af_g, size_t lda,
        const bf16* __restrict__ Bh_g, const bf16* __restrict__ Bl_g,
        const float* __restrict__ Bf_g, size_t ldb,
        float* __restrict__ Cf, bf16* __restrict__ Ch, bf16* __restrict__ Cl,
        size_t ldc,
        const float* __restrict__ fcos, const float* __restrict__ fsin,
        int crow0, int ccol0, int kceil) {
    constexpr int APAD = 40;
    constexpr int BPAD = BN + 8;
    constexpr int ASZ  = BM * APAD;
    constexpr int BSZ_ = 32 * BPAD;
    constexpr int BUFSZ = 2 * ASZ + 2 * BSZ_;
    constexpr int N8A = BM / 64 > 0 ? BM / 64 : 1;
    constexpr int N4A = BM / 32;
    constexpr int N8B = BN / 64;
    constexpr int N4B = BN / 32;
    constexpr int WR = BM / 32;
    constexpr int NI = WNW / 16;
    static_assert(WR * (BN / WNW) == 8, "need 8 warps");

    extern __shared__ char smraw[];
    bf16* smbase = (bf16*)smraw;

    int tid = threadIdx.x;
    int w = tid >> 5;
    int wm = w % WR;
    int wn = w / WR;

    wmma::fragment<wmma::accumulator, 16, 16, 16, float> acc[2][NI];
#pragma unroll
    for (int mi = 0; mi < 2; mi++)
#pragma unroll
        for (int ni = 0; ni < NI; ni++) wmma::fill_fragment(acc[mi][ni], 0.0f);

    uint4 rah[PA ? N8A : 1], ral[PA ? N8A : 1];
    float4 raf[PA ? 1 : N4A];
    uint4 rbh[PB ? N8B : 1], rbl[PB ? N8B : 1];
    float4 rbf[PB ? 1 : N4B];

    // ---- prefetch chunk 0
    if constexpr (PA) {
#pragma unroll
        for (int it = 0; it < N8A; it++) {
            int idx8 = tid + it * 256;
            int row = idx8 >> 2, kc = (idx8 & 3) * 8;
            rah[it] = *(const uint4*)&Ah_g[(size_t)row * lda + kc];
            ral[it] = *(const uint4*)&Al_g[(size_t)row * lda + kc];
        }
    } else {
#pragma unroll
        for (int it = 0; it < N4A; it++) {
            int idx4 = tid + it * 256;
            int row = idx4 >> 3, kc = (idx4 & 7) * 4;
            raf[it] = *(const float4*)&Af_g[(size_t)row * lda + kc];
        }
    }
    if constexpr (PB) {
#pragma unroll
        for (int it = 0; it < N8B; it++) {
            int idx8 = tid + it * 256;
            int row = idx8 / (BN / 8), nc = (idx8 % (BN / 8)) * 8;
            rbh[it] = *(const uint4*)&Bh_g[(size_t)row * ldb + nc];
            rbl[it] = *(const uint4*)&Bl_g[(size_t)row * ldb + nc];
        }
    } else {
#pragma unroll
        for (int it = 0; it < N4B; it++) {
            int idx4 = tid + it * 256;
            int row = idx4 / (BN / 4), nc = (idx4 % (BN / 4)) * 4;
            rbf[it] = *(const float4*)&Bf_g[(size_t)row * ldb + nc];
        }
    }

    int nch = kceil >> 5;
    int cur = 0;
    for (int ch = 0; ch < nch; ch++) {
        bf16* Ah = smbase + cur * BUFSZ;
        bf16* Al = Ah + ASZ;
        bf16* Bh = Al + ASZ;
        bf16* Bl = Bh + BSZ_;

        if constexpr (PA) {
#pragma unroll
            for (int it = 0; it < N8A; it++) {
                int idx8 = tid + it * 256;
                int row = idx8 >> 2, kc = (idx8 & 3) * 8;
                *(uint4*)&Ah[row * APAD + kc] = rah[it];
                *(uint4*)&Al[row * APAD + kc] = ral[it];
            }
        } else {
#pragma unroll
            for (int it = 0; it < N4A; it++) {
                int idx4 = tid + it * 256;
                int row = idx4 >> 3, kc = (idx4 & 7) * 4;
                split_write4(Ah, Al, row * APAD + kc, raf[it]);
            }
        }
        if constexpr (PB) {
#pragma unroll
            for (int it = 0; it < N8B; it++) {
                int idx8 = tid + it * 256;
                int row = idx8 / (BN / 8), nc = (idx8 % (BN / 8)) * 8;
                *(uint4*)&Bh[row * BPAD + nc] = rbh[it];
                *(uint4*)&Bl[row * BPAD + nc] = rbl[it];
            }
        } else {
#pragma unroll
            for (int it = 0; it < N4B; it++) {
                int idx4 = tid + it * 256;
                int row = idx4 / (BN / 4), nc = (idx4 % (BN / 4)) * 4;
                split_write4(Bh, Bl, row * BPAD + nc, rbf[it]);
            }
        }
        __syncthreads();

        if (ch + 1 < nch) {
            int k0 = (ch + 1) * 32;
            if constexpr (PA) {
#pragma unroll
                for (int it = 0; it < N8A; it++) {
                    int idx8 = tid + it * 256;
                    int row = idx8 >> 2, kc = (idx8 & 3) * 8;
                    rah[it] = *(const uint4*)&Ah_g[(size_t)row * lda + k0 + kc];
                    ral[it] = *(const uint4*)&Al_g[(size_t)row * lda + k0 + kc];
                }
            } else {
#pragma unroll
                for (int it = 0; it < N4A; it++) {
                    int idx4 = tid + it * 256;
                    int row = idx4 >> 3, kc = (idx4 & 7) * 4;
                    raf[it] = *(const float4*)&Af_g[(size_t)row * lda + k0 + kc];
                }
            }
            if constexpr (PB) {
#pragma unroll
                for (int it = 0; it < N8B; it++) {
                    int idx8 = tid + it * 256;
                    int row = idx8 / (BN / 8), nc = (idx8 % (BN / 8)) * 8;
                    rbh[it] = *(const uint4*)&Bh_g[(size_t)(k0 + row) * ldb + nc];
                    rbl[it] = *(const uint4*)&Bl_g[(size_t)(k0 + row) * ldb + nc];
                }
            } else {
#pragma unroll
                for (int it = 0; it < N4B; it++) {
                    int idx4 = tid + it * 256;
                    int row = idx4 / (BN / 4), nc = (idx4 % (BN / 4)) * 4;
                    rbf[it] = *(const float4*)&Bf_g[(size_t)(k0 + row) * ldb + nc];
                }
            }
        }

#pragma unroll
        for (int kk = 0; kk < 32; kk += 16) {
            wmma::fragment<wmma::matrix_a, 16, 16, 16, bf16, wmma::row_major> ah[2], al[2];
#pragma unroll
            for (int mi = 0; mi < 2; mi++) {
                int r0 = (wm * 32 + mi * 16) * APAD + kk;
                wmma::load_matrix_sync(ah[mi], Ah + r0, APAD);
                wmma::load_matrix_sync(al[mi], Al + r0, APAD);
            }
#pragma unroll
            for (int ni = 0; ni < NI; ni++) {
                wmma::fragment<wmma::matrix_b, 16, 16, 16, bf16, wmma::row_major> bh, bl;
                int c0 = kk * BPAD + wn * WNW + ni * 16;
                wmma::load_matrix_sync(bh, Bh + c0, BPAD);
                wmma::load_matrix_sync(bl, Bl + c0, BPAD);
#pragma unroll
                for (int mi = 0; mi < 2; mi++) {
                    wmma::mma_sync(acc[mi][ni], ah[mi], bh, acc[mi][ni]);
                    wmma::mma_sync(acc[mi][ni], ah[mi], bl, acc[mi][ni]);
                    wmma::mma_sync(acc[mi][ni], al[mi], bh, acc[mi][ni]);
                }
            }
        }
        cur ^= 1;
    }

    // ---- epilogue via fp32 smem staging
    __syncthreads();
    float* stg = (float*)smraw;
#pragma unroll
    for (int mi = 0; mi < 2; mi++)
#pragma unroll
        for (int ni = 0; ni < NI; ni++)
            wmma::store_matrix_sync(stg + (size_t)(wm * 32 + mi * 16) * BN + wn * WNW + ni * 16,
                                    acc[mi][ni], BN, wmma::mem_row_major);
    __syncthreads();
    constexpr int NE4 = BM * BN / 1024;
#pragma unroll
    for (int it = 0; it < NE4; it++) {
        int idx4 = tid + it * 256;
        int row = idx4 / (BN / 4), c = (idx4 % (BN / 4)) * 4;
        float4 v = *(const float4*)&stg[row * BN + c];
        if constexpr (EPI == 2) {
            int pos = (crow0 + row) & (SEQ - 1);
            int p = ((ccol0 + c) & 63) >> 1;
            float c0v = fcos[pos * 32 + p],     s0v = fsin[pos * 32 + p];
            float c1v = fcos[pos * 32 + p + 1], s1v = fsin[pos * 32 + p + 1];
            float4 o;
            o.x = v.x * c0v - v.y * s0v;
            o.y = v.x * s0v + v.y * c0v;
            o.z = v.z * c1v - v.w * s1v;
            o.w = v.z * s1v + v.w * c1v;
            v = o;
        }
        if constexpr (EPI == 1) {
            split_write4(Ch, Cl, (size_t)row * ldc + c, v);
        } else {
            *(float4*)&Cf[(size_t)row * ldc + c] = v;
        }
    }
}

// smem byte sizes
#define SM_BIG  ((2*(128*40) + 2*(32*136)) * 2 * 2)   // 75776 (stage 64KB fits)
#define SM_WS2  ((2*(64*40)  + 2*(32*264)) * 2 * 2)   // 88064 (stage 64KB fits)
#define SM_WSV  ((2*(128*40) + 2*(32*72))  * 2 * 2)   // 59392 (stage 32KB fits)

// ======================= GEMM wrappers =====================================
// Q projection with fused RoPE: C fp32 [2048,1024]
__global__ __launch_bounds__(256) void gemm_projq(const bf16* __restrict__ Ah,
                                                  const bf16* __restrict__ Al,
                                                  const bf16* __restrict__ Bh,
                                                  const bf16* __restrict__ Bl,
                                                  float* __restrict__ C,
                                                  const float* __restrict__ fcos,
                                                  const float* __restrict__ fsin) {
    size_t ao = (size_t)blockIdx.y * 128 * DM;
    size_t bo = (size_t)blockIdx.x * 128;
    float* Cb = C + (size_t)blockIdx.y * 128 * DM + (size_t)blockIdx.x * 128;
    gcore<128, 128, 64, true, true, 2>(Ah + ao, Al + ao, nullptr, DM,
                                       Bh + bo, Bl + bo, nullptr, DM,
                                       Cb, nullptr, nullptr, DM,
                                       fcos, fsin, blockIdx.y * 128, blockIdx.x * 128, DM);
}

// K projection with fused RoPE: C fp32 [2048,256]
__global__ __launch_bounds__(256) void gemm_projk(const bf16* __restrict__ Ah,
                                                  const bf16* __restrict__ Al,
                                                  const bf16* __restrict__ Bh,
                                                  const bf16* __restrict__ Bl,
                                                  float* __restrict__ C,
                                                  const float* __restrict__ fcos,
                                                  const float* __restrict__ fsin) {
    size_t ao = (size_t)blockIdx.y * 128 * DM;
    size_t bo = (size_t)blockIdx.x * 128;
    float* Cb = C + (size_t)blockIdx.y * 128 * 256 + (size_t)blockIdx.x * 128;
    gcore<128, 128, 64, true, true, 2>(Ah + ao, Al + ao, nullptr, DM,
                                       Bh + bo, Bl + bo, nullptr, 256,
                                       Cb, nullptr, nullptr, 256,
                                       fcos, fsin, blockIdx.y * 128, blockIdx.x * 128, DM);
}

// Output projection: C fp32 [2048,1024]
__global__ __launch_bounds__(256) void gemm_wo(const bf16* __restrict__ Ah,
                                               const bf16* __restrict__ Al,
                                               const bf16* __restrict__ Bh,
                                               const bf16* __restrict__ Bl,
                                               float* __restrict__ C) {
    size_t ao = (size_t)blockIdx.y * 128 * DM;
    size_t bo = (size_t)blockIdx.x * 128;
    float* Cb = C + (size_t)blockIdx.y * 128 * DM + (size_t)blockIdx.x * 128;
    gcore<128, 128, 64, true, true, 0>(Ah + ao, Al + ao, nullptr, DM,
                                       Bh + bo, Bl + bo, nullptr, DM,
                                       Cb, nullptr, nullptr, DM,
                                       nullptr, nullptr, 0, 0, DM);
}

// ws: per-i batched, A=attn pre-split, B=symbols f32, C bf16 pair; tile 64x256
__global__ __launch_bounds__(256) void gemm_ws(const bf16* __restrict__ ah,
                                               const bf16* __restrict__ al,
                                               const float* __restrict__ symbols,
                                               bf16* __restrict__ wsh,
                                               bf16* __restrict__ wsl) {
    int i = blockIdx.y;
    int c0 = blockIdx.x * 256;
    int kceil = (i + 32) & ~31;              // attn[j>i]==0 exactly
    size_t ao = (size_t)i * SEQ;
    const float* B = symbols + (size_t)i * SEQ * DM + c0;
    size_t co = (size_t)i * DM + c0;
    gcore<64, 256, 64, true, false, 1>(ah + ao, al + ao, nullptr, (size_t)SEQ * SEQ,
                                       nullptr, nullptr, B, DM,
                                       nullptr, wsh + co, wsl + co, (size_t)SEQ * DM,
                                       nullptr, nullptr, 0, 0, kceil);
}

// wsv: A=ws pre-split, B=wv pre-split, C bf16 pair; tile 128x64
__global__ __launch_bounds__(256) void gemm_wsv(const bf16* __restrict__ wsh,
                                                const bf16* __restrict__ wsl,
                                                const bf16* __restrict__ wvh,
                                                const bf16* __restrict__ wvl,
                                                bf16* __restrict__ oph,
                                                bf16* __restrict__ opl) {
    int i0 = blockIdx.x * 128;
    int row = blockIdx.y;
    int b = row >> 4, h = row & 15, kv = h >> 2;
    size_t ao = ((size_t)row * SEQ + i0) * DM;
    size_t bo = (size_t)kv * HD;
    size_t co = ((size_t)b * SEQ + i0) * DM + h * HD;
    gcore<128, 64, 32, true, true, 1>(wsh + ao, wsl + ao, nullptr, DM,
                                      wvh + bo, wvl + bo, nullptr, NKV * HD,
                                      nullptr, oph + co, opl + co, DM,
                                      nullptr, nullptr, 0, 0, DM);
}

// ======================= K transpose =======================================
__global__ void transpose_k(const float* __restrict__ xk, float* __restrict__ xkT) {
    int idx = blockIdx.x * blockDim.x + threadIdx.x;
    if (idx >= BSZ * NKV * HD * SEQ) return;
    int j = idx & 511;
    int d = (idx >> 9) & 63;
    int kv = (idx >> 15) & 3;
    int b = idx >> 17;
    xkT[idx] = xk[((size_t)(b * SEQ + j)) * (NKV * HD) + kv * HD + d];
}

// ======================= Scores + causal softmax (+ split write) ===========
__global__ __launch_bounds__(256) void scores_softmax(const float* __restrict__ xq,
                                                      const float* __restrict__ xkT,
                                                      float* __restrict__ attn,
                                                      bf16* __restrict__ ah_g,
                                                      bf16* __restrict__ al_g) {
    int i = blockIdx.x, h = blockIdx.y, b = blockIdx.z;
    int kv = h >> 2;
    int tid = threadIdx.x;
    __shared__ float qs[HD];
    __shared__ float red[256];
    if (tid < HD) qs[tid] = xq[((size_t)(b * SEQ + i)) * DM + h * HD + tid];
    __syncthreads();
    int nj = i + 1;
    const float* kT = xkT + ((size_t)(b * NKV + kv)) * HD * SEQ;
    float sc[2];
#pragma unroll
    for (int t = 0; t < 2; t++) {
        int j = tid + t * 256;
        float acc = -INFINITY;
        if (j < nj) {
            acc = 0.f;
#pragma unroll
            for (int d = 0; d < HD; d++) acc += qs[d] * kT[d * SEQ + j];
            acc *= 0.125f;
        }
        sc[t] = acc;
    }
    float m = fmaxf(sc[0], sc[1]);
    red[tid] = m;
    __syncthreads();
    for (int s2 = 128; s2 > 0; s2 >>= 1) {
        if (tid < s2) red[tid] = fmaxf(red[tid], red[tid + s2]);
        __syncthreads();
    }
    m = red[0];
    __syncthreads();
    float e[2];
#pragma unroll
    for (int t = 0; t < 2; t++) {
        int j = tid + t * 256;
        e[t] = (j < nj) ? expf(sc[t] - m) : 0.f;
    }
    red[tid] = e[0] + e[1];
    __syncthreads();
    for (int s2 = 128; s2 > 0; s2 >>= 1) {
        if (tid < s2) red[tid] += red[tid + s2];
        __syncthreads();
    }
    float inv = 1.0f / red[0];
    size_t base = ((size_t)((b * NH + h) * SEQ + i)) * SEQ;
#pragma unroll
    for (int t = 0; t < 2; t++) {
        int j = tid + t * 256;
        float a = e[t] * inv;
        attn[base + j] = a;
        bf16 hh = __float2bfloat16(a);
        ah_g[base + j] = hh;
        al_g[base + j] = __float2bfloat16(a - __bfloat162float(hh));
    }
}

// ===========================================================================
extern "C" void kernel_launch(void* const* d_in, const int* in_sizes, int n_in,
                              void* d_out, int out_size) {
    const float* x       = (const float*)d_in[0];
    const float* symbols = (const float*)d_in[1];
    const float* fcos    = (const float*)d_in[2];
    const float* fsin    = (const float*)d_in[3];
    const float* wq      = (const float*)d_in[4];
    const float* wk      = (const float*)d_in[5];
    const float* wv      = (const float*)d_in[6];
    const float* wo      = (const float*)d_in[7];

    float* out  = (float*)d_out;
    float* attn = out + OUT_ELEMS;

    float *p_xq, *p_xk, *p_xkT;
    bf16 *p_xh, *p_xl, *p_wqh, *p_wql, *p_wkh, *p_wkl, *p_wvh, *p_wvl, *p_woh, *p_wol;
    bf16 *p_ah, *p_al, *p_wsh, *p_wsl, *p_oph, *p_opl;
    cudaGetSymbolAddress((void**)&p_xq, g_xq);
    cudaGetSymbolAddress((void**)&p_xk, g_xk);
    cudaGetSymbolAddress((void**)&p_xkT, g_xkT);
    cudaGetSymbolAddress((void**)&p_xh, g_xh);   cudaGetSymbolAddress((void**)&p_xl, g_xl);
    cudaGetSymbolAddress((void**)&p_wqh, g_wqh); cudaGetSymbolAddress((void**)&p_wql, g_wql);
    cudaGetSymbolAddress((void**)&p_wkh, g_wkh); cudaGetSymbolAddress((void**)&p_wkl, g_wkl);
    cudaGetSymbolAddress((void**)&p_wvh, g_wvh); cudaGetSymbolAddress((void**)&p_wvl, g_wvl);
    cudaGetSymbolAddress((void**)&p_woh, g_woh); cudaGetSymbolAddress((void**)&p_wol, g_wol);
    cudaGetSymbolAddress((void**)&p_ah, g_ah);   cudaGetSymbolAddress((void**)&p_al, g_al);
    cudaGetSymbolAddress((void**)&p_wsh, g_wsh); cudaGetSymbolAddress((void**)&p_wsl, g_wsl);
    cudaGetSymbolAddress((void**)&p_oph, g_oph); cudaGetSymbolAddress((void**)&p_opl, g_opl);

    cudaFuncSetAttribute(gemm_projq, cudaFuncAttributeMaxDynamicSharedMemorySize, SM_BIG);
    cudaFuncSetAttribute(gemm_projk, cudaFuncAttributeMaxDynamicSharedMemorySize, SM_BIG);
    cudaFuncSetAttribute(gemm_wo,    cudaFuncAttributeMaxDynamicSharedMemorySize, SM_BIG);
    cudaFuncSetAttribute(gemm_ws,    cudaFuncAttributeMaxDynamicSharedMemorySize, SM_WS2);
    cudaFuncSetAttribute(gemm_wsv,   cudaFuncAttributeMaxDynamicSharedMemorySize, SM_WSV);

    // Launch order puts gemm_projq at index 2 (ncu captures launch idx 2).
    prep_split<<<(NROWS * DM / 4 + 255) / 256, 256>>>(x, p_xh, p_xl, NROWS * DM / 4);       // 0
    prep_split<<<(DM * DM / 4 + 255) / 256, 256>>>(wq, p_wqh, p_wql, DM * DM / 4);          // 1
    gemm_projq<<<dim3(DM / 128, NROWS / 128), 256, SM_BIG>>>(p_xh, p_xl, p_wqh, p_wql,      // 2
                                                             p_xq, fcos, fsin);
    prep_split<<<(DM * NKV * HD / 4 + 255) / 256, 256>>>(wk, p_wkh, p_wkl, DM * NKV * HD / 4); // 3
    gemm_projk<<<dim3(256 / 128, NROWS / 128), 256, SM_BIG>>>(p_xh, p_xl, p_wkh, p_wkl,     // 4
                                                              p_xk, fcos, fsin);
    prep_split<<<(DM * NKV * HD / 4 + 255) / 256, 256>>>(wv, p_wvh, p_wvl, DM * NKV * HD / 4); // 5
    prep_split<<<(DM * DM / 4 + 255) / 256, 256>>>(wo, p_woh, p_wol, DM * DM / 4);          // 6

    transpose_k<<<(BSZ * NKV * HD * SEQ + 255) / 256, 256>>>(p_xk, p_xkT);                  // 7
    scores_softmax<<<dim3(SEQ, NH, BSZ), 256>>>(p_xq, p_xkT, attn, p_ah, p_al);             // 8

    gemm_ws<<<dim3(DM / 256, SEQ), 256, SM_WS2>>>(p_ah, p_al, symbols, p_wsh, p_wsl);       // 9
    gemm_wsv<<<dim3(SEQ / 128, 64), 256, SM_WSV>>>(p_wsh, p_wsl, p_wvh, p_wvl, p_oph, p_opl); // 10
    gemm_wo<<<dim3(DM / 128, NROWS / 128), 256, SM_BIG>>>(p_oph, p_opl, p_woh, p_wol, out); // 11
}

// round 9
// speedup vs baseline: 3.6239x; 1.0482x over previous
#include <cuda_runtime.h>
#include <cuda_bf16.h>
#include <mma.h>
#include <math.h>
#include <cstdint>

using namespace nvcuda;

#define BSZ 4
#define SEQ 512
#define DM 1024
#define NH 16
#define NKV 4
#define HD 64
#define NROWS (BSZ*SEQ)          // 2048
#define OUT_ELEMS (BSZ*SEQ*DM)

typedef __nv_bfloat16 bf16;

// Scratch (device globals; no runtime allocation allowed)
__device__ float g_xq[NROWS * DM];                  // 8 MB (post-rope)
__device__ float g_xk[NROWS * (NKV*HD)];            // 2 MB (post-rope)
__device__ float g_xkT[BSZ * NKV * HD * SEQ];       // 2 MB
__device__ bf16 g_xh[NROWS * DM],  g_xl[NROWS * DM];
__device__ bf16 g_wqh[DM * DM],    g_wql[DM * DM];
__device__ bf16 g_wkh[DM * NKV*HD], g_wkl[DM * NKV*HD];
__device__ bf16 g_wvh[DM * NKV*HD], g_wvl[DM * NKV*HD];
__device__ bf16 g_woh[DM * DM],    g_wol[DM * DM];
__device__ bf16 g_ah[(size_t)64 * SEQ * SEQ], g_al[(size_t)64 * SEQ * SEQ];
__device__ bf16 g_wsh[(size_t)64 * SEQ * DM], g_wsl[(size_t)64 * SEQ * DM];
__device__ bf16 g_oph[NROWS * DM], g_opl[NROWS * DM];

// ===========================================================================
// split helpers
// ===========================================================================
__device__ __forceinline__ void split_write4(bf16* __restrict__ H, bf16* __restrict__ L,
                                             size_t off, float4 v) {
    bf16 h0 = __float2bfloat16(v.x);
    bf16 h1 = __float2bfloat16(v.y);
    bf16 h2 = __float2bfloat16(v.z);
    bf16 h3 = __float2bfloat16(v.w);
    __nv_bfloat162 hh0; hh0.x = h0; hh0.y = h1;
    __nv_bfloat162 hh1; hh1.x = h2; hh1.y = h3;
    *(__nv_bfloat162*)(H + off)     = hh0;
    *(__nv_bfloat162*)(H + off + 2) = hh1;
    __nv_bfloat162 ll0, ll1;
    ll0.x = __float2bfloat16(v.x - __bfloat162float(h0));
    ll0.y = __float2bfloat16(v.y - __bfloat162float(h1));
    ll1.x = __float2bfloat16(v.z - __bfloat162float(h2));
    ll1.y = __float2bfloat16(v.w - __bfloat162float(h3));
    *(__nv_bfloat162*)(L + off)     = ll0;
    *(__nv_bfloat162*)(L + off + 2) = ll1;
}

__global__ void prep_split(const float* __restrict__ src,
                           bf16* __restrict__ h, bf16* __restrict__ l, int n4) {
    int idx = blockIdx.x * blockDim.x + threadIdx.x;
    if (idx >= n4) return;
    float4 v = ((const float4*)src)[idx];
    split_write4(h, l, (size_t)idx * 4, v);
}

// ===========================================================================
// Generalized WMMA GEMM core. 3-term bf16 split (AhBh + AhBl + AlBh), fp32 acc.
// 8 warps, warp tile 32 x WNW; CTA tile BM x BN; BK=32 double-buffered.
// PA/PB: operand pre-split (h,l) bf16 (pure smem copy). Else f32 + in-loop cvt.
// EPI: 0 = fp32 out, 1 = bf16 (h,l) out, 2 = fp32 out with fused RoPE.
// ===========================================================================
template<int BM, int BN, int WNW, bool PA, bool PB, int EPI>
__device__ __forceinline__ void gcore(
        const bf16* __restrict__ Ah_g, const bf16* __restrict__ Al_g,
        const float* __restrict__ Af_g, size_t lda,
        const bf16* __restrict__ Bh_g, const bf16* __restrict__ Bl_g,
        const float* __restrict__ Bf_g, size_t ldb,
        float* __restrict__ Cf, bf16* __restrict__ Ch, bf16* __restrict__ Cl,
        size_t ldc,
        const float* __restrict__ fcos, const float* __restrict__ fsin,
        int crow0, int ccol0, int kceil) {
    constexpr int APAD = 40;
    constexpr int BPAD = BN + 8;
    constexpr int ASZ  = BM * APAD;
    constexpr int BSZ_ = 32 * BPAD;
    constexpr int BUFSZ = 2 * ASZ + 2 * BSZ_;
    constexpr int N8A = BM / 64 > 0 ? BM / 64 : 1;
    constexpr int N4A = BM / 32;
    constexpr int N8B = BN / 64;
    constexpr int N4B = BN / 32;
    constexpr int WR = BM / 32;
    constexpr int NI = WNW / 16;
    static_assert(WR * (BN / WNW) == 8, "need 8 warps");

    extern __shared__ char smraw[];
    bf16* smbase = (bf16*)smraw;

    int tid = threadIdx.x;
    int w = tid >> 5;
    int wm = w % WR;
    int wn = w / WR;

    wmma::fragment<wmma::accumulator, 16, 16, 16, float> acc[2][NI];
#pragma unroll
    for (int mi = 0; mi < 2; mi++)
#pragma unroll
        for (int ni = 0; ni < NI; ni++) wmma::fill_fragment(acc[mi][ni], 0.0f);

    uint4 rah[PA ? N8A : 1], ral[PA ? N8A : 1];
    float4 raf[PA ? 1 : N4A];
    uint4 rbh[PB ? N8B : 1], rbl[PB ? N8B : 1];
    float4 rbf[PB ? 1 : N4B];

    if constexpr (PA) {
#pragma unroll
        for (int it = 0; it < N8A; it++) {
            int idx8 = tid + it * 256;
            int row = idx8 >> 2, kc = (idx8 & 3) * 8;
            rah[it] = *(const uint4*)&Ah_g[(size_t)row * lda + kc];
            ral[it] = *(const uint4*)&Al_g[(size_t)row * lda + kc];
        }
    } else {
#pragma unroll
        for (int it = 0; it < N4A; it++) {
            int idx4 = tid + it * 256;
            int row = idx4 >> 3, kc = (idx4 & 7) * 4;
            raf[it] = *(const float4*)&Af_g[(size_t)row * lda + kc];
        }
    }
    if constexpr (PB) {
#pragma unroll
        for (int it = 0; it < N8B; it++) {
            int idx8 = tid + it * 256;
            int row = idx8 / (BN / 8), nc = (idx8 % (BN / 8)) * 8;
            rbh[it] = *(const uint4*)&Bh_g[(size_t)row * ldb + nc];
            rbl[it] = *(const uint4*)&Bl_g[(size_t)row * ldb + nc];
        }
    } else {
#pragma unroll
        for (int it = 0; it < N4B; it++) {
            int idx4 = tid + it * 256;
            int row = idx4 / (BN / 4), nc = (idx4 % (BN / 4)) * 4;
            rbf[it] = *(const float4*)&Bf_g[(size_t)row * ldb + nc];
        }
    }

    int nch = kceil >> 5;
    int cur = 0;
    for (int ch = 0; ch < nch; ch++) {
        bf16* Ah = smbase + cur * BUFSZ;
        bf16* Al = Ah + ASZ;
        bf16* Bh = Al + ASZ;
        bf16* Bl = Bh + BSZ_;

        if constexpr (PA) {
#pragma unroll
            for (int it = 0; it < N8A; it++) {
                int idx8 = tid + it * 256;
                int row = idx8 >> 2, kc = (idx8 & 3) * 8;
                *(uint4*)&Ah[row * APAD + kc] = rah[it];
                *(uint4*)&Al[row * APAD + kc] = ral[it];
            }
        } else {
#pragma unroll
            for (int it = 0; it < N4A; it++) {
                int idx4 = tid + it * 256;
                int row = idx4 >> 3, kc = (idx4 & 7) * 4;
                split_write4(Ah, Al, row * APAD + kc, raf[it]);
            }
        }
        if constexpr (PB) {
#pragma unroll
            for (int it = 0; it < N8B; it++) {
                int idx8 = tid + it * 256;
                int row = idx8 / (BN / 8), nc = (idx8 % (BN / 8)) * 8;
                *(uint4*)&Bh[row * BPAD + nc] = rbh[it];
                *(uint4*)&Bl[row * BPAD + nc] = rbl[it];
            }
        } else {
#pragma unroll
            for (int it = 0; it < N4B; it++) {
                int idx4 = tid + it * 256;
                int row = idx4 / (BN / 4), nc = (idx4 % (BN / 4)) * 4;
                split_write4(Bh, Bl, row * BPAD + nc, rbf[it]);
            }
        }
        __syncthreads();

        if (ch + 1 < nch) {
            int k0 = (ch + 1) * 32;
            if constexpr (PA) {
#pragma unroll
                for (int it = 0; it < N8A; it++) {
                    int idx8 = tid + it * 256;
                    int row = idx8 >> 2, kc = (idx8 & 3) * 8;
                    rah[it] = *(const uint4*)&Ah_g[(size_t)row * lda + k0 + kc];
                    ral[it] = *(const uint4*)&Al_g[(size_t)row * lda + k0 + kc];
                }
            } else {
#pragma unroll
                for (int it = 0; it < N4A; it++) {
                    int idx4 = tid + it * 256;
                    int row = idx4 >> 3, kc = (idx4 & 7) * 4;
                    raf[it] = *(const float4*)&Af_g[(size_t)row * lda + k0 + kc];
                }
            }
            if constexpr (PB) {
#pragma unroll
                for (int it = 0; it < N8B; it++) {
                    int idx8 = tid + it * 256;
                    int row = idx8 / (BN / 8), nc = (idx8 % (BN / 8)) * 8;
                    rbh[it] = *(const uint4*)&Bh_g[(size_t)(k0 + row) * ldb + nc];
                    rbl[it] = *(const uint4*)&Bl_g[(size_t)(k0 + row) * ldb + nc];
                }
            } else {
#pragma unroll
                for (int it = 0; it < N4B; it++) {
                    int idx4 = tid + it * 256;
                    int row = idx4 / (BN / 4), nc = (idx4 % (BN / 4)) * 4;
                    rbf[it] = *(const float4*)&Bf_g[(size_t)(k0 + row) * ldb + nc];
                }
            }
        }

#pragma unroll
        for (int kk = 0; kk < 32; kk += 16) {
            wmma::fragment<wmma::matrix_a, 16, 16, 16, bf16, wmma::row_major> ah[2], al[2];
#pragma unroll
            for (int mi = 0; mi < 2; mi++) {
                int r0 = (wm * 32 + mi * 16) * APAD + kk;
                wmma::load_matrix_sync(ah[mi], Ah + r0, APAD);
                wmma::load_matrix_sync(al[mi], Al + r0, APAD);
            }
#pragma unroll
            for (int ni = 0; ni < NI; ni++) {
                wmma::fragment<wmma::matrix_b, 16, 16, 16, bf16, wmma::row_major> bh, bl;
                int c0 = kk * BPAD + wn * WNW + ni * 16;
                wmma::load_matrix_sync(bh, Bh + c0, BPAD);
                wmma::load_matrix_sync(bl, Bl + c0, BPAD);
#pragma unroll
                for (int mi = 0; mi < 2; mi++) {
                    wmma::mma_sync(acc[mi][ni], ah[mi], bh, acc[mi][ni]);
                    wmma::mma_sync(acc[mi][ni], ah[mi], bl, acc[mi][ni]);
                    wmma::mma_sync(acc[mi][ni], al[mi], bh, acc[mi][ni]);
                }
            }
        }
        cur ^= 1;
    }

    // ---- epilogue via fp32 smem staging
    __syncthreads();
    float* stg = (float*)smraw;
#pragma unroll
    for (int mi = 0; mi < 2; mi++)
#pragma unroll
        for (int ni = 0; ni < NI; ni++)
            wmma::store_matrix_sync(stg + (size_t)(wm * 32 + mi * 16) * BN + wn * WNW + ni * 16,
                                    acc[mi][ni], BN, wmma::mem_row_major);
    __syncthreads();
    constexpr int NE4 = BM * BN / 1024;
#pragma unroll
    for (int it = 0; it < NE4; it++) {
        int idx4 = tid + it * 256;
        int row = idx4 / (BN / 4), c = (idx4 % (BN / 4)) * 4;
        float4 v = *(const float4*)&stg[row * BN + c];
        if constexpr (EPI == 2) {
            int pos = (crow0 + row) & (SEQ - 1);
            int p = ((ccol0 + c) & 63) >> 1;
            float c0v = fcos[pos * 32 + p],     s0v = fsin[pos * 32 + p];
            float c1v = fcos[pos * 32 + p + 1], s1v = fsin[pos * 32 + p + 1];
            float4 o;
            o.x = v.x * c0v - v.y * s0v;
            o.y = v.x * s0v + v.y * c0v;
            o.z = v.z * c1v - v.w * s1v;
            o.w = v.z * s1v + v.w * c1v;
            v = o;
        }
        if constexpr (EPI == 1) {
            split_write4(Ch, Cl, (size_t)row * ldc + c, v);
        } else {
            *(float4*)&Cf[(size_t)row * ldc + c] = v;
        }
    }
}

// smem byte sizes
#define SM_BIG  ((2*(128*40) + 2*(32*136)) * 2 * 2)   // 75776
#define SM_WS2  ((2*(64*40)  + 2*(32*264)) * 2 * 2)   // 88064
#define SM_WSV  ((2*(128*40) + 2*(32*72))  * 2 * 2)   // 59392

// ======================= GEMM wrappers =====================================
__global__ __launch_bounds__(256) void gemm_projq(const bf16* __restrict__ Ah,
                                                  const bf16* __restrict__ Al,
                                                  const bf16* __restrict__ Bh,
                                                  const bf16* __restrict__ Bl,
                                                  float* __restrict__ C,
                                                  const float* __restrict__ fcos,
                                                  const float* __restrict__ fsin) {
    size_t ao = (size_t)blockIdx.y * 128 * DM;
    size_t bo = (size_t)blockIdx.x * 128;
    float* Cb = C + (size_t)blockIdx.y * 128 * DM + (size_t)blockIdx.x * 128;
    gcore<128, 128, 64, true, true, 2>(Ah + ao, Al + ao, nullptr, DM,
                                       Bh + bo, Bl + bo, nullptr, DM,
                                       Cb, nullptr, nullptr, DM,
                                       fcos, fsin, blockIdx.y * 128, blockIdx.x * 128, DM);
}

__global__ __launch_bounds__(256) void gemm_projk(const bf16* __restrict__ Ah,
                                                  const bf16* __restrict__ Al,
                                                  const bf16* __restrict__ Bh,
                                                  const bf16* __restrict__ Bl,
                                                  float* __restrict__ C,
                                                  const float* __restrict__ fcos,
                                                  const float* __restrict__ fsin) {
    size_t ao = (size_t)blockIdx.y * 128 * DM;
    size_t bo = (size_t)blockIdx.x * 128;
    float* Cb = C + (size_t)blockIdx.y * 128 * 256 + (size_t)blockIdx.x * 128;
    gcore<128, 128, 64, true, true, 2>(Ah + ao, Al + ao, nullptr, DM,
                                       Bh + bo, Bl + bo, nullptr, 256,
                                       Cb, nullptr, nullptr, 256,
                                       fcos, fsin, blockIdx.y * 128, blockIdx.x * 128, DM);
}

__global__ __launch_bounds__(256) void gemm_wo(const bf16* __restrict__ Ah,
                                               const bf16* __restrict__ Al,
                                               const bf16* __restrict__ Bh,
                                               const bf16* __restrict__ Bl,
                                               float* __restrict__ C) {
    size_t ao = (size_t)blockIdx.y * 128 * DM;
    size_t bo = (size_t)blockIdx.x * 128;
    float* Cb = C + (size_t)blockIdx.y * 128 * DM + (size_t)blockIdx.x * 128;
    gcore<128, 128, 64, true, true, 0>(Ah + ao, Al + ao, nullptr, DM,
                                       Bh + bo, Bl + bo, nullptr, DM,
                                       Cb, nullptr, nullptr, DM,
                                       nullptr, nullptr, 0, 0, DM);
}

__global__ __launch_bounds__(256) void gemm_ws(const bf16* __restrict__ ah,
                                               const bf16* __restrict__ al,
                                               const float* __restrict__ symbols,
                                               bf16* __restrict__ wsh,
                                               bf16* __restrict__ wsl) {
    int i = blockIdx.y;
    int c0 = blockIdx.x * 256;
    int kceil = (i + 32) & ~31;              // attn[j>i]==0 exactly
    size_t ao = (size_t)i * SEQ;
    const float* B = symbols + (size_t)i * SEQ * DM + c0;
    size_t co = (size_t)i * DM + c0;
    gcore<64, 256, 64, true, false, 1>(ah + ao, al + ao, nullptr, (size_t)SEQ * SEQ,
                                       nullptr, nullptr, B, DM,
                                       nullptr, wsh + co, wsl + co, (size_t)SEQ * DM,
                                       nullptr, nullptr, 0, 0, kceil);
}

__global__ __launch_bounds__(256) void gemm_wsv(const bf16* __restrict__ wsh,
                                                const bf16* __restrict__ wsl,
                                                const bf16* __restrict__ wvh,
                                                const bf16* __restrict__ wvl,
                                                bf16* __restrict__ oph,
                                                bf16* __restrict__ opl) {
    int i0 = blockIdx.x * 128;
    int row = blockIdx.y;
    int b = row >> 4, h = row & 15, kv = h >> 2;
    size_t ao = ((size_t)row * SEQ + i0) * DM;
    size_t bo = (size_t)kv * HD;
    size_t co = ((size_t)b * SEQ + i0) * DM + h * HD;
    gcore<128, 64, 32, true, true, 1>(wsh + ao, wsl + ao, nullptr, DM,
                                      wvh + bo, wvl + bo, nullptr, NKV * HD,
                                      nullptr, oph + co, opl + co, DM,
                                      nullptr, nullptr, 0, 0, DM);
}

// ======================= K transpose =======================================
__global__ void transpose_k(const float* __restrict__ xk, float* __restrict__ xkT) {
    int idx = blockIdx.x * blockDim.x + threadIdx.x;
    if (idx >= BSZ * NKV * HD * SEQ) return;
    int j = idx & 511;
    int d = (idx >> 9) & 63;
    int kv = (idx >> 15) & 3;
    int b = idx >> 17;
    xkT[idx] = xk[((size_t)(b * SEQ + j)) * (NKV * HD) + kv * HD + d];
}

// ======================= Scores + softmax v2 (16-i tile, warp-per-row) =====
// grid (SEQ/16, NH, BSZ), 256 threads = 8 warps, each warp owns 2 i-rows.
// Lane j ownership: j = q4*128 + lane*4 + e  (q4 in 0..3, e in 0..3).
__global__ __launch_bounds__(256) void scores2(const float* __restrict__ xq,
                                               const float* __restrict__ xkT,
                                               float* __restrict__ attn,
                                               bf16* __restrict__ ah_g,
                                               bf16* __restrict__ al_g) {
    int i0 = blockIdx.x * 16;
    int h = blockIdx.y, b = blockIdx.z;
    int kv = h >> 2;
    int tid = threadIdx.x;
    int w = tid >> 5, lane = tid & 31;

    __shared__ float qs[16][HD];
    {
        int idx = tid * 4;
        int row = idx >> 6, d = idx & 63;
        *(float4*)&qs[row][d] =
            *(const float4*)&xq[((size_t)(b * SEQ + i0 + row)) * DM + h * HD + d];
    }
    __syncthreads();

    int ia = i0 + w * 2;
    int ib = ia + 1;
    const float* kT = xkT + ((size_t)(b * NKV + kv)) * HD * SEQ;

    float sa[16], sb[16];
#pragma unroll
    for (int t = 0; t < 16; t++) { sa[t] = 0.f; sb[t] = 0.f; }

    const float* qra = qs[w * 2];
    const float* qrb = qs[w * 2 + 1];
#pragma unroll 4
    for (int d = 0; d < HD; d++) {
        float qa = qra[d];
        float qb = qrb[d];
        const float* kd = kT + (size_t)d * SEQ + lane * 4;
#pragma unroll
        for (int q4 = 0; q4 < 4; q4++) {
            float4 kv4 = *(const float4*)&kd[q4 * 128];
            sa[q4 * 4 + 0] += qa * kv4.x;  sb[q4 * 4 + 0] += qb * kv4.x;
            sa[q4 * 4 + 1] += qa * kv4.y;  sb[q4 * 4 + 1] += qb * kv4.y;
            sa[q4 * 4 + 2] += qa * kv4.z;  sb[q4 * 4 + 2] += qb * kv4.z;
            sa[q4 * 4 + 3] += qa * kv4.w;  sb[q4 * 4 + 3] += qb * kv4.w;
        }
    }

    // mask + scale
    float ma = -INFINITY, mb = -INFINITY;
#pragma unroll
    for (int q4 = 0; q4 < 4; q4++)
#pragma unroll
        for (int e = 0; e < 4; e++) {
            int j = q4 * 128 + lane * 4 + e;
            int t = q4 * 4 + e;
            sa[t] = (j <= ia) ? sa[t] * 0.125f : -INFINITY;
            sb[t] = (j <= ib) ? sb[t] * 0.125f : -INFINITY;
            ma = fmaxf(ma, sa[t]);
            mb = fmaxf(mb, sb[t]);
        }
#pragma unroll
    for (int o = 16; o > 0; o >>= 1) {
        ma = fmaxf(ma, __shfl_xor_sync(0xFFFFFFFF, ma, o));
        mb = fmaxf(mb, __shfl_xor_sync(0xFFFFFFFF, mb, o));
    }
    float suma = 0.f, sumb = 0.f;
#pragma unroll
    for (int t = 0; t < 16; t++) {
        sa[t] = (sa[t] == -INFINITY) ? 0.f : __expf(sa[t] - ma);
        sb[t] = (sb[t] == -INFINITY) ? 0.f : __expf(sb[t] - mb);
        suma += sa[t];
        sumb += sb[t];
    }
#pragma unroll
    for (int o = 16; o > 0; o >>= 1) {
        suma += __shfl_xor_sync(0xFFFFFFFF, suma, o);
        sumb += __shfl_xor_sync(0xFFFFFFFF, sumb, o);
    }
    float inva = 1.0f / suma;
    float invb = 1.0f / sumb;

    size_t basea = ((size_t)((b * NH + h) * SEQ + ia)) * SEQ;
    size_t baseb = basea + SEQ;
#pragma unroll
    for (int q4 = 0; q4 < 4; q4++) {
        int j = q4 * 128 + lane * 4;
        float4 va = make_float4(sa[q4 * 4] * inva, sa[q4 * 4 + 1] * inva,
                                sa[q4 * 4 + 2] * inva, sa[q4 * 4 + 3] * inva);
        float4 vb = make_float4(sb[q4 * 4] * invb, sb[q4 * 4 + 1] * invb,
                                sb[q4 * 4 + 2] * invb, sb[q4 * 4 + 3] * invb);
        *(float4*)&attn[basea + j] = va;
        *(float4*)&attn[baseb + j] = vb;
        split_write4(ah_g, al_g, basea + j, va);
        split_write4(ah_g, al_g, baseb + j, vb);
    }
}

// ===========================================================================
extern "C" void kernel_launch(void* const* d_in, const int* in_sizes, int n_in,
                              void* d_out, int out_size) {
    const float* x       = (const float*)d_in[0];
    const float* symbols = (const float*)d_in[1];
    const float* fcos    = (const float*)d_in[2];
    const float* fsin    = (const float*)d_in[3];
    const float* wq      = (const float*)d_in[4];
    const float* wk      = (const float*)d_in[5];
    const float* wv      = (const float*)d_in[6];
    const float* wo      = (const float*)d_in[7];

    float* out  = (float*)d_out;
    float* attn = out + OUT_ELEMS;

    float *p_xq, *p_xk, *p_xkT;
    bf16 *p_xh, *p_xl, *p_wqh, *p_wql, *p_wkh, *p_wkl, *p_wvh, *p_wvl, *p_woh, *p_wol;
    bf16 *p_ah, *p_al, *p_wsh, *p_wsl, *p_oph, *p_opl;
    cudaGetSymbolAddress((void**)&p_xq, g_xq);
    cudaGetSymbolAddress((void**)&p_xk, g_xk);
    cudaGetSymbolAddress((void**)&p_xkT, g_xkT);
    cudaGetSymbolAddress((void**)&p_xh, g_xh);   cudaGetSymbolAddress((void**)&p_xl, g_xl);
    cudaGetSymbolAddress((void**)&p_wqh, g_wqh); cudaGetSymbolAddress((void**)&p_wql, g_wql);
    cudaGetSymbolAddress((void**)&p_wkh, g_wkh); cudaGetSymbolAddress((void**)&p_wkl, g_wkl);
    cudaGetSymbolAddress((void**)&p_wvh, g_wvh); cudaGetSymbolAddress((void**)&p_wvl, g_wvl);
    cudaGetSymbolAddress((void**)&p_woh, g_woh); cudaGetSymbolAddress((void**)&p_wol, g_wol);
    cudaGetSymbolAddress((void**)&p_ah, g_ah);   cudaGetSymbolAddress((void**)&p_al, g_al);
    cudaGetSymbolAddress((void**)&p_wsh, g_wsh); cudaGetSymbolAddress((void**)&p_wsl, g_wsl);
    cudaGetSymbolAddress((void**)&p_oph, g_oph); cudaGetSymbolAddress((void**)&p_opl, g_opl);

    cudaFuncSetAttribute(gemm_projq, cudaFuncAttributeMaxDynamicSharedMemorySize, SM_BIG);
    cudaFuncSetAttribute(gemm_projk, cudaFuncAttributeMaxDynamicSharedMemorySize, SM_BIG);
    cudaFuncSetAttribute(gemm_wo,    cudaFuncAttributeMaxDynamicSharedMemorySize, SM_BIG);
    cudaFuncSetAttribute(gemm_ws,    cudaFuncAttributeMaxDynamicSharedMemorySize, SM_WS2);
    cudaFuncSetAttribute(gemm_wsv,   cudaFuncAttributeMaxDynamicSharedMemorySize, SM_WSV);

    // Launch order: ncu (-s 5 -c 1) captures launch index 5 -> gemm_projq.
    prep_split<<<(NROWS * DM / 4 + 255) / 256, 256>>>(x, p_xh, p_xl, NROWS * DM / 4);          // 0
    prep_split<<<(DM * DM / 4 + 255) / 256, 256>>>(wq, p_wqh, p_wql, DM * DM / 4);             // 1
    prep_split<<<(DM * NKV * HD / 4 + 255) / 256, 256>>>(wk, p_wkh, p_wkl, DM * NKV * HD / 4); // 2
    prep_split<<<(DM * NKV * HD / 4 + 255) / 256, 256>>>(wv, p_wvh, p_wvl, DM * NKV * HD / 4); // 3
    prep_split<<<(DM * DM / 4 + 255) / 256, 256>>>(wo, p_woh, p_wol, DM * DM / 4);             // 4
    gemm_projq<<<dim3(DM / 128, NROWS / 128), 256, SM_BIG>>>(p_xh, p_xl, p_wqh, p_wql,         // 5
                                                             p_xq, fcos, fsin);
    gemm_projk<<<dim3(256 / 128, NROWS / 128), 256, SM_BIG>>>(p_xh, p_xl, p_wkh, p_wkl,        // 6
                                                              p_xk, fcos, fsin);
    transpose_k<<<(BSZ * NKV * HD * SEQ + 255) / 256, 256>>>(p_xk, p_xkT);                     // 7
    scores2<<<dim3(SEQ / 16, NH, BSZ), 256>>>(p_xq, p_xkT, attn, p_ah, p_al);                  // 8
    gemm_ws<<<dim3(DM / 256, SEQ), 256, SM_WS2>>>(p_ah, p_al, symbols, p_wsh, p_wsl);          // 9
    gemm_wsv<<<dim3(SEQ / 128, 64), 256, SM_WSV>>>(p_wsh, p_wsl, p_wvh, p_wvl, p_oph, p_opl);  // 10
    gemm_wo<<<dim3(DM / 128, NROWS / 128), 256, SM_BIG>>>(p_oph, p_opl, p_woh, p_wol, out);    // 11
}

// round 10
// speedup vs baseline: 4.5465x; 1.2546x over previous
#include <cuda_runtime.h>
#include <cuda_bf16.h>
#include <mma.h>
#include <math.h>
#include <cstdint>

using namespace nvcuda;

#define BSZ 4
#define SEQ 512
#define DM 1024
#define NH 16
#define NKV 4
#define HD 64
#define NROWS (BSZ*SEQ)          // 2048
#define OUT_ELEMS (BSZ*SEQ*DM)

typedef __nv_bfloat16 bf16;

// Scratch (device globals; no runtime allocation allowed)
__device__ float g_xq[NROWS * DM];                  // 8 MB (post-rope)
__device__ float g_xk[NROWS * (NKV*HD)];            // 2 MB (post-rope)
__device__ float g_xkT[BSZ * NKV * HD * SEQ];       // 2 MB
__device__ bf16 g_xh[NROWS * DM],  g_xl[NROWS * DM];
__device__ bf16 g_wqh[DM * DM],    g_wql[DM * DM];
__device__ bf16 g_wkh[DM * NKV*HD], g_wkl[DM * NKV*HD];
__device__ bf16 g_wvh[DM * NKV*HD], g_wvl[DM * NKV*HD];
__device__ bf16 g_woh[DM * DM],    g_wol[DM * DM];
__device__ bf16 g_ah[(size_t)64 * SEQ * SEQ], g_al[(size_t)64 * SEQ * SEQ];
__device__ bf16 g_wsh[(size_t)64 * SEQ * DM], g_wsl[(size_t)64 * SEQ * DM];
__device__ bf16 g_oph[NROWS * DM], g_opl[NROWS * DM];

// ===========================================================================
// helpers
// ===========================================================================
__device__ __forceinline__ void split_write4(bf16* __restrict__ H, bf16* __restrict__ L,
                                             size_t off, float4 v) {
    bf16 h0 = __float2bfloat16(v.x);
    bf16 h1 = __float2bfloat16(v.y);
    bf16 h2 = __float2bfloat16(v.z);
    bf16 h3 = __float2bfloat16(v.w);
    __nv_bfloat162 hh0; hh0.x = h0; hh0.y = h1;
    __nv_bfloat162 hh1; hh1.x = h2; hh1.y = h3;
    *(__nv_bfloat162*)(H + off)     = hh0;
    *(__nv_bfloat162*)(H + off + 2) = hh1;
    __nv_bfloat162 ll0, ll1;
    ll0.x = __float2bfloat16(v.x - __bfloat162float(h0));
    ll0.y = __float2bfloat16(v.y - __bfloat162float(h1));
    ll1.x = __float2bfloat16(v.z - __bfloat162float(h2));
    ll1.y = __float2bfloat16(v.w - __bfloat162float(h3));
    *(__nv_bfloat162*)(L + off)     = ll0;
    *(__nv_bfloat162*)(L + off + 2) = ll1;
}

__device__ __forceinline__ void cp_async16(uint32_t saddr, const void* gptr) {
    asm volatile("cp.async.cg.shared.global [%0], [%1], 16;" :: "r"(saddr), "l"(gptr));
}
__device__ __forceinline__ void cp_commit() { asm volatile("cp.async.commit_group;"); }
__device__ __forceinline__ void cp_wait0()  { asm volatile("cp.async.wait_group 0;"); }

// ======================= merged operand prep ===============================
__global__ void prep_all(const float* __restrict__ x, const float* __restrict__ wq,
                         const float* __restrict__ wk, const float* __restrict__ wv,
                         const float* __restrict__ wo,
                         bf16* xh, bf16* xl, bf16* wqh, bf16* wql,
                         bf16* wkh, bf16* wkl, bf16* wvh, bf16* wvl,
                         bf16* woh, bf16* wol) {
    int idx = blockIdx.x * blockDim.x + threadIdx.x;
    const float* src; bf16 *H, *L; int base;
    if (idx < 524288)       { src = x;  H = xh;  L = xl;  base = 0; }
    else if (idx < 786432)  { src = wq; H = wqh; L = wql; base = 524288; }
    else if (idx < 851968)  { src = wk; H = wkh; L = wkl; base = 786432; }
    else if (idx < 917504)  { src = wv; H = wvh; L = wvl; base = 851968; }
    else if (idx < 1179648) { src = wo; H = woh; L = wol; base = 917504; }
    else return;
    int o = idx - base;
    float4 v = ((const float4*)src)[o];
    split_write4(H, L, (size_t)o * 4, v);
}

// ===========================================================================
// WMMA GEMM core. 3-term bf16 split (AhBh + AhBl + AlBh), fp32 acc.
// 8 warps, warp tile 32 x WNW; CTA tile BM x BN; BK=32 double-buffered.
// PA/PB: operand pre-split (h,l) bf16 -> loaded straight to smem via cp.async.
//        otherwise f32, register-staged with in-loop conversion.
// EPI: 0 = fp32 out, 1 = bf16 (h,l) out, 2 = fp32 out with fused RoPE.
// ===========================================================================
template<int BM, int BN, int WNW, bool PA, bool PB, int EPI>
__device__ __forceinline__ void gcore(
        const bf16* __restrict__ Ah_g, const bf16* __restrict__ Al_g,
        const float* __restrict__ Af_g, size_t lda,
        const bf16* __restrict__ Bh_g, const bf16* __restrict__ Bl_g,
        const float* __restrict__ Bf_g, size_t ldb,
        float* __restrict__ Cf, bf16* __restrict__ Ch, bf16* __restrict__ Cl,
        size_t ldc,
        const float* __restrict__ fcos, const float* __restrict__ fsin,
        int crow0, int ccol0, int kceil) {
    constexpr int APAD = 40;
    constexpr int BPAD = BN + 8;
    constexpr int ASZ  = BM * APAD;
    constexpr int BSZ_ = 32 * BPAD;
    constexpr int BUFSZ = 2 * ASZ + 2 * BSZ_;
    constexpr int N8A = BM / 64 > 0 ? BM / 64 : 1;
    constexpr int N4A = BM / 32;
    constexpr int N8B = BN / 64;
    constexpr int N4B = BN / 32;
    constexpr int WR = BM / 32;
    constexpr int NI = WNW / 16;
    static_assert(WR * (BN / WNW) == 8, "need 8 warps");

    extern __shared__ char smraw[];
    bf16* smbase = (bf16*)smraw;
    uint32_t smu = (uint32_t)__cvta_generic_to_shared(smbase);

    int tid = threadIdx.x;
    int w = tid >> 5;
    int wm = w % WR;
    int wn = w / WR;

    wmma::fragment<wmma::accumulator, 16, 16, 16, float> acc[2][NI];
#pragma unroll
    for (int mi = 0; mi < 2; mi++)
#pragma unroll
        for (int ni = 0; ni < NI; ni++) wmma::fill_fragment(acc[mi][ni], 0.0f);

    float4 raf[PA ? 1 : N4A];
    float4 rbf[PB ? 1 : N4B];

    // async issue helpers (16B granules straight to smem)
    auto issueA = [&](int k0, int bufsel) {
#pragma unroll
        for (int it = 0; it < N8A; it++) {
            int idx8 = tid + it * 256;
            int row = idx8 >> 2, kc = (idx8 & 3) * 8;
            uint32_t so = smu + (uint32_t)(bufsel * BUFSZ + row * APAD + kc) * 2;
            cp_async16(so, Ah_g + (size_t)row * lda + k0 + kc);
            cp_async16(so + ASZ * 2, Al_g + (size_t)row * lda + k0 + kc);
        }
    };
    auto issueB = [&](int k0, int bufsel) {
#pragma unroll
        for (int it = 0; it < N8B; it++) {
            int idx8 = tid + it * 256;
            int row = idx8 / (BN / 8), nc = (idx8 % (BN / 8)) * 8;
            uint32_t so = smu + (uint32_t)(bufsel * BUFSZ + 2 * ASZ + row * BPAD + nc) * 2;
            cp_async16(so, Bh_g + (size_t)(k0 + row) * ldb + nc);
            cp_async16(so + BSZ_ * 2, Bl_g + (size_t)(k0 + row) * ldb + nc);
        }
    };

    int nch = kceil >> 5;
    int cur = 0;

    // prologue: chunk 0
    if constexpr (PA) issueA(0, 0);
    if constexpr (PB) issueB(0, 0);
    if constexpr (PA || PB) cp_commit();
    if constexpr (!PA) {
#pragma unroll
        for (int it = 0; it < N4A; it++) {
            int idx4 = tid + it * 256;
            int row = idx4 >> 3, kc = (idx4 & 7) * 4;
            raf[it] = *(const float4*)&Af_g[(size_t)row * lda + kc];
        }
    }
    if constexpr (!PB) {
#pragma unroll
        for (int it = 0; it < N4B; it++) {
            int idx4 = tid + it * 256;
            int row = idx4 / (BN / 4), nc = (idx4 % (BN / 4)) * 4;
            rbf[it] = *(const float4*)&Bf_g[(size_t)row * ldb + nc];
        }
    }

    for (int ch = 0; ch < nch; ch++) {
        bf16* Ah = smbase + cur * BUFSZ;
        bf16* Al = Ah + ASZ;
        bf16* Bh = Al + ASZ;
        bf16* Bl = Bh + BSZ_;

        // f32-staged operands: convert + store for this chunk
        if constexpr (!PA) {
#pragma unroll
            for (int it = 0; it < N4A; it++) {
                int idx4 = tid + it * 256;
                int row = idx4 >> 3, kc = (idx4 & 7) * 4;
                split_write4(Ah, Al, row * APAD + kc, raf[it]);
            }
        }
        if constexpr (!PB) {
#pragma unroll
            for (int it = 0; it < N4B; it++) {
                int idx4 = tid + it * 256;
                int row = idx4 / (BN / 4), nc = (idx4 % (BN / 4)) * 4;
                split_write4(Bh, Bl, row * BPAD + nc, rbf[it]);
            }
        }
        if constexpr (PA || PB) cp_wait0();
        __syncthreads();

        // issue next chunk (overlaps with MMA below)
        if (ch + 1 < nch) {
            int k0 = (ch + 1) * 32;
            if constexpr (PA) issueA(k0, cur ^ 1);
            if constexpr (PB) issueB(k0, cur ^ 1);
            if constexpr (PA || PB) cp_commit();
            if constexpr (!PA) {
#pragma unroll
                for (int it = 0; it < N4A; it++) {
                    int idx4 = tid + it * 256;
                    int row = idx4 >> 3, kc = (idx4 & 7) * 4;
                    raf[it] = *(const float4*)&Af_g[(size_t)row * lda + k0 + kc];
                }
            }
            if constexpr (!PB) {
#pragma unroll
                for (int it = 0; it < N4B; it++) {
                    int idx4 = tid + it * 256;
                    int row = idx4 / (BN / 4), nc = (idx4 % (BN / 4)) * 4;
                    rbf[it] = *(const float4*)&Bf_g[(size_t)(k0 + row) * ldb + nc];
                }
            }
        }

#pragma unroll
        for (int kk = 0; kk < 32; kk += 16) {
            wmma::fragment<wmma::matrix_a, 16, 16, 16, bf16, wmma::row_major> ah[2], al[2];
#pragma unroll
            for (int mi = 0; mi < 2; mi++) {
                int r0 = (wm * 32 + mi * 16) * APAD + kk;
                wmma::load_matrix_sync(ah[mi], Ah + r0, APAD);
                wmma::load_matrix_sync(al[mi], Al + r0, APAD);
            }
#pragma unroll
            for (int ni = 0; ni < NI; ni++) {
                wmma::fragment<wmma::matrix_b, 16, 16, 16, bf16, wmma::row_major> bh, bl;
                int c0 = kk * BPAD + wn * WNW + ni * 16;
                wmma::load_matrix_sync(bh, Bh + c0, BPAD);
                wmma::load_matrix_sync(bl, Bl + c0, BPAD);
#pragma unroll
                for (int mi = 0; mi < 2; mi++) {
                    wmma::mma_sync(acc[mi][ni], ah[mi], bh, acc[mi][ni]);
                    wmma::mma_sync(acc[mi][ni], ah[mi], bl, acc[mi][ni]);
                    wmma::mma_sync(acc[mi][ni], al[mi], bh, acc[mi][ni]);
                }
            }
        }
        cur ^= 1;
    }

    // ---- epilogue via fp32 smem staging
    __syncthreads();
    float* stg = (float*)smraw;
#pragma unroll
    for (int mi = 0; mi < 2; mi++)
#pragma unroll
        for (int ni = 0; ni < NI; ni++)
            wmma::store_matrix_sync(stg + (size_t)(wm * 32 + mi * 16) * BN + wn * WNW + ni * 16,
                                    acc[mi][ni], BN, wmma::mem_row_major);
    __syncthreads();
    constexpr int NE4 = BM * BN / 1024;
#pragma unroll
    for (int it = 0; it < NE4; it++) {
        int idx4 = tid + it * 256;
        int row = idx4 / (BN / 4), c = (idx4 % (BN / 4)) * 4;
        float4 v = *(const float4*)&stg[row * BN + c];
        if constexpr (EPI == 2) {
            int pos = (crow0 + row) & (SEQ - 1);
            int p = ((ccol0 + c) & 63) >> 1;
            float c0v = fcos[pos * 32 + p],     s0v = fsin[pos * 32 + p];
            float c1v = fcos[pos * 32 + p + 1], s1v = fsin[pos * 32 + p + 1];
            float4 o;
            o.x = v.x * c0v - v.y * s0v;
            o.y = v.x * s0v + v.y * c0v;
            o.z = v.z * c1v - v.w * s1v;
            o.w = v.z * s1v + v.w * c1v;
            v = o;
        }
        if constexpr (EPI == 1) {
            split_write4(Ch, Cl, (size_t)row * ldc + c, v);
        } else {
            *(float4*)&Cf[(size_t)row * ldc + c] = v;
        }
    }
}

// smem byte sizes
#define SM_BIG  ((2*(128*40) + 2*(32*136)) * 2 * 2)   // 75776
#define SM_WS2  ((2*(64*40)  + 2*(32*264)) * 2 * 2)   // 88064
#define SM_WSV  ((2*(128*40) + 2*(32*72))  * 2 * 2)   // 59392

// ======================= GEMM wrappers =====================================
__global__ __launch_bounds__(256) void gemm_projq(const bf16* __restrict__ Ah,
                                                  const bf16* __restrict__ Al,
                                                  const bf16* __restrict__ Bh,
                                                  const bf16* __restrict__ Bl,
                                                  float* __restrict__ C,
                                                  const float* __restrict__ fcos,
                                                  const float* __restrict__ fsin) {
    size_t ao = (size_t)blockIdx.y * 128 * DM;
    size_t bo = (size_t)blockIdx.x * 128;
    float* Cb = C + (size_t)blockIdx.y * 128 * DM + (size_t)blockIdx.x * 128;
    gcore<128, 128, 64, true, true, 2>(Ah + ao, Al + ao, nullptr, DM,
                                       Bh + bo, Bl + bo, nullptr, DM,
                                       Cb, nullptr, nullptr, DM,
                                       fcos, fsin, blockIdx.y * 128, blockIdx.x * 128, DM);
}

__global__ __launch_bounds__(256) void gemm_projk(const bf16* __restrict__ Ah,
                                                  const bf16* __restrict__ Al,
                                                  const bf16* __restrict__ Bh,
                                                  const bf16* __restrict__ Bl,
                                                  float* __restrict__ C,
                                                  const float* __restrict__ fcos,
                                                  const float* __restrict__ fsin) {
    size_t ao = (size_t)blockIdx.y * 128 * DM;
    size_t bo = (size_t)blockIdx.x * 128;
    float* Cb = C + (size_t)blockIdx.y * 128 * 256 + (size_t)blockIdx.x * 128;
    gcore<128, 128, 64, true, true, 2>(Ah + ao, Al + ao, nullptr, DM,
                                       Bh + bo, Bl + bo, nullptr, 256,
                                       Cb, nullptr, nullptr, 256,
                                       fcos, fsin, blockIdx.y * 128, blockIdx.x * 128, DM);
}

__global__ __launch_bounds__(256) void gemm_wo(const bf16* __restrict__ Ah,
                                               const bf16* __restrict__ Al,
                                               const bf16* __restrict__ Bh,
                                               const bf16* __restrict__ Bl,
                                               float* __restrict__ C) {
    size_t ao = (size_t)blockIdx.y * 128 * DM;
    size_t bo = (size_t)blockIdx.x * 128;
    float* Cb = C + (size_t)blockIdx.y * 128 * DM + (size_t)blockIdx.x * 128;
    gcore<128, 128, 64, true, true, 0>(Ah + ao, Al + ao, nullptr, DM,
                                       Bh + bo, Bl + bo, nullptr, DM,
                                       Cb, nullptr, nullptr, DM,
                                       nullptr, nullptr, 0, 0, DM);
}

__global__ __launch_bounds__(256) void gemm_ws(const bf16* __restrict__ ah,
                                               const bf16* __restrict__ al,
                                               const float* __restrict__ symbols,
                                               bf16* __restrict__ wsh,
                                               bf16* __restrict__ wsl) {
    int i = blockIdx.y;
    int c0 = blockIdx.x * 256;
    int kceil = (i + 32) & ~31;              // attn[j>i]==0 exactly
    size_t ao = (size_t)i * SEQ;
    const float* B = symbols + (size_t)i * SEQ * DM + c0;
    size_t co = (size_t)i * DM + c0;
    gcore<64, 256, 64, true, false, 1>(ah + ao, al + ao, nullptr, (size_t)SEQ * SEQ,
                                       nullptr, nullptr, B, DM,
                                       nullptr, wsh + co, wsl + co, (size_t)SEQ * DM,
                                       nullptr, nullptr, 0, 0, kceil);
}

__global__ __launch_bounds__(256) void gemm_wsv(const bf16* __restrict__ wsh,
                                                const bf16* __restrict__ wsl,
                                                const bf16* __restrict__ wvh,
                                                const bf16* __restrict__ wvl,
                                                bf16* __restrict__ oph,
                                                bf16* __restrict__ opl) {
    int i0 = blockIdx.x * 128;
    int row = blockIdx.y;
    int b = row >> 4, h = row & 15, kv = h >> 2;
    size_t ao = ((size_t)row * SEQ + i0) * DM;
    size_t bo = (size_t)kv * HD;
    size_t co = ((size_t)b * SEQ + i0) * DM + h * HD;
    gcore<128, 64, 32, true, true, 1>(wsh + ao, wsl + ao, nullptr, DM,
                                      wvh + bo, wvl + bo, nullptr, NKV * HD,
                                      nullptr, oph + co, opl + co, DM,
                                      nullptr, nullptr, 0, 0, DM);
}

// ======================= K transpose =======================================
__global__ void transpose_k(const float* __restrict__ xk, float* __restrict__ xkT) {
    int idx = blockIdx.x * blockDim.x + threadIdx.x;
    if (idx >= BSZ * NKV * HD * SEQ) return;
    int j = idx & 511;
    int d = (idx >> 9) & 63;
    int kv = (idx >> 15) & 3;
    int b = idx >> 17;
    xkT[idx] = xk[((size_t)(b * SEQ + j)) * (NKV * HD) + kv * HD + d];
}

// ======================= Scores + softmax (causal-skipped) =================
template<int NQ4>
__device__ __forceinline__ void scores_body(int i0, const float qra[HD], const float qrb[HD],
                                            const float* __restrict__ kT,
                                            int ia, int ib, int lane,
                                            float* __restrict__ attn,
                                            bf16* __restrict__ ah_g,
                                            bf16* __restrict__ al_g,
                                            size_t basea, size_t baseb) {
    float sa[NQ4 * 4], sb[NQ4 * 4];
#pragma unroll
    for (int t = 0; t < NQ4 * 4; t++) { sa[t] = 0.f; sb[t] = 0.f; }

#pragma unroll 4
    for (int d = 0; d < HD; d++) {
        float qa = qra[d];
        float qb = qrb[d];
        const float* kd = kT + (size_t)d * SEQ + lane * 4;
#pragma unroll
        for (int q4 = 0; q4 < NQ4; q4++) {
            float4 kv4 = *(const float4*)&kd[q4 * 128];
            sa[q4 * 4 + 0] += qa * kv4.x;  sb[q4 * 4 + 0] += qb * kv4.x;
            sa[q4 * 4 + 1] += qa * kv4.y;  sb[q4 * 4 + 1] += qb * kv4.y;
            sa[q4 * 4 + 2] += qa * kv4.z;  sb[q4 * 4 + 2] += qb * kv4.z;
            sa[q4 * 4 + 3] += qa * kv4.w;  sb[q4 * 4 + 3] += qb * kv4.w;
        }
    }

    float ma = -INFINITY, mb = -INFINITY;
#pragma unroll
    for (int q4 = 0; q4 < NQ4; q4++)
#pragma unroll
        for (int e = 0; e < 4; e++) {
            int j = q4 * 128 + lane * 4 + e;
            int t = q4 * 4 + e;
            sa[t] = (j <= ia) ? sa[t] * 0.125f : -INFINITY;
            sb[t] = (j <= ib) ? sb[t] * 0.125f : -INFINITY;
            ma = fmaxf(ma, sa[t]);
            mb = fmaxf(mb, sb[t]);
        }
#pragma unroll
    for (int o = 16; o > 0; o >>= 1) {
        ma = fmaxf(ma, __shfl_xor_sync(0xFFFFFFFF, ma, o));
        mb = fmaxf(mb, __shfl_xor_sync(0xFFFFFFFF, mb, o));
    }
    float suma = 0.f, sumb = 0.f;
#pragma unroll
    for (int t = 0; t < NQ4 * 4; t++) {
        sa[t] = (sa[t] == -INFINITY) ? 0.f : __expf(sa[t] - ma);
        sb[t] = (sb[t] == -INFINITY) ? 0.f : __expf(sb[t] - mb);
        suma += sa[t];
        sumb += sb[t];
    }
#pragma unroll
    for (int o = 16; o > 0; o >>= 1) {
        suma += __shfl_xor_sync(0xFFFFFFFF, suma, o);
        sumb += __shfl_xor_sync(0xFFFFFFFF, sumb, o);
    }
    float inva = 1.0f / suma;
    float invb = 1.0f / sumb;

#pragma unroll
    for (int q4 = 0; q4 < NQ4; q4++) {
        int j = q4 * 128 + lane * 4;
        float4 va = make_float4(sa[q4 * 4] * inva, sa[q4 * 4 + 1] * inva,
                                sa[q4 * 4 + 2] * inva, sa[q4 * 4 + 3] * inva);
        float4 vb = make_float4(sb[q4 * 4] * invb, sb[q4 * 4 + 1] * invb,
                                sb[q4 * 4 + 2] * invb, sb[q4 * 4 + 3] * invb);
        *(float4*)&attn[basea + j] = va;
        *(float4*)&attn[baseb + j] = vb;
        split_write4(ah_g, al_g, basea + j, va);
        split_write4(ah_g, al_g, baseb + j, vb);
    }
    // zero-fill skipped causal region of the fp32 attn output
    float4 z = make_float4(0.f, 0.f, 0.f, 0.f);
#pragma unroll
    for (int q4 = NQ4; q4 < 4; q4++) {
        int j = q4 * 128 + lane * 4;
        *(float4*)&attn[basea + j] = z;
        *(float4*)&attn[baseb + j] = z;
    }
}

__global__ __launch_bounds__(256) void scores2(const float* __restrict__ xq,
                                               const float* __restrict__ xkT,
                                               float* __restrict__ attn,
                                               bf16* __restrict__ ah_g,
                                               bf16* __restrict__ al_g) {
    int i0 = blockIdx.x * 16;
    int h = blockIdx.y, b = blockIdx.z;
    int kv = h >> 2;
    int tid = threadIdx.x;
    int w = tid >> 5, lane = tid & 31;

    __shared__ float qs[16][HD];
    {
        int idx = tid * 4;
        int row = idx >> 6, d = idx & 63;
        *(float4*)&qs[row][d] =
            *(const float4*)&xq[((size_t)(b * SEQ + i0 + row)) * DM + h * HD + d];
    }
    __syncthreads();

    int ia = i0 + w * 2;
    int ib = ia + 1;
    const float* kT = xkT + ((size_t)(b * NKV + kv)) * HD * SEQ;
    size_t basea = ((size_t)((b * NH + h) * SEQ + ia)) * SEQ;
    size_t baseb = basea + SEQ;
    int nq4 = min(4, (i0 + 16 + 127) >> 7);

    switch (nq4) {
        case 1: scores_body<1>(i0, qs[w*2], qs[w*2+1], kT, ia, ib, lane, attn, ah_g, al_g, basea, baseb); break;
        case 2: scores_body<2>(i0, qs[w*2], qs[w*2+1], kT, ia, ib, lane, attn, ah_g, al_g, basea, baseb); break;
        case 3: scores_body<3>(i0, qs[w*2], qs[w*2+1], kT, ia, ib, lane, attn, ah_g, al_g, basea, baseb); break;
        default: scores_body<4>(i0, qs[w*2], qs[w*2+1], kT, ia, ib, lane, attn, ah_g, al_g, basea, baseb); break;
    }
}

// ===========================================================================
extern "C" void kernel_launch(void* const* d_in, const int* in_sizes, int n_in,
                              void* d_out, int out_size) {
    const float* x       = (const float*)d_in[0];
    const float* symbols = (const float*)d_in[1];
    const float* fcos    = (const float*)d_in[2];
    const float* fsin    = (const float*)d_in[3];
    const float* wq      = (const float*)d_in[4];
    const float* wk      = (const float*)d_in[5];
    const float* wv      = (const float*)d_in[6];
    const float* wo      = (const float*)d_in[7];

    float* out  = (float*)d_out;
    float* attn = out + OUT_ELEMS;

    float *p_xq, *p_xk, *p_xkT;
    bf16 *p_xh, *p_xl, *p_wqh, *p_wql, *p_wkh, *p_wkl, *p_wvh, *p_wvl, *p_woh, *p_wol;
    bf16 *p_ah, *p_al, *p_wsh, *p_wsl, *p_oph, *p_opl;
    cudaGetSymbolAddress((void**)&p_xq, g_xq);
    cudaGetSymbolAddress((void**)&p_xk, g_xk);
    cudaGetSymbolAddress((void**)&p_xkT, g_xkT);
    cudaGetSymbolAddress((void**)&p_xh, g_xh);   cudaGetSymbolAddress((void**)&p_xl, g_xl);
    cudaGetSymbolAddress((void**)&p_wqh, g_wqh); cudaGetSymbolAddress((void**)&p_wql, g_wql);
    cudaGetSymbolAddress((void**)&p_wkh, g_wkh); cudaGetSymbolAddress((void**)&p_wkl, g_wkl);
    cudaGetSymbolAddress((void**)&p_wvh, g_wvh); cudaGetSymbolAddress((void**)&p_wvl, g_wvl);
    cudaGetSymbolAddress((void**)&p_woh, g_woh); cudaGetSymbolAddress((void**)&p_wol, g_wol);
    cudaGetSymbolAddress((void**)&p_ah, g_ah);   cudaGetSymbolAddress((void**)&p_al, g_al);
    cudaGetSymbolAddress((void**)&p_wsh, g_wsh); cudaGetSymbolAddress((void**)&p_wsl, g_wsl);
    cudaGetSymbolAddress((void**)&p_oph, g_oph); cudaGetSymbolAddress((void**)&p_opl, g_opl);

    cudaFuncSetAttribute(gemm_projq, cudaFuncAttributeMaxDynamicSharedMemorySize, SM_BIG);
    cudaFuncSetAttribute(gemm_projk, cudaFuncAttributeMaxDynamicSharedMemorySize, SM_BIG);
    cudaFuncSetAttribute(gemm_wo,    cudaFuncAttributeMaxDynamicSharedMemorySize, SM_BIG);
    cudaFuncSetAttribute(gemm_ws,    cudaFuncAttributeMaxDynamicSharedMemorySize, SM_WS2);
    cudaFuncSetAttribute(gemm_wsv,   cudaFuncAttributeMaxDynamicSharedMemorySize, SM_WSV);

    prep_all<<<4608, 256>>>(x, wq, wk, wv, wo, p_xh, p_xl, p_wqh, p_wql,
                            p_wkh, p_wkl, p_wvh, p_wvl, p_woh, p_wol);          // 0
    gemm_projq<<<dim3(DM / 128, NROWS / 128), 256, SM_BIG>>>(p_xh, p_xl, p_wqh, p_wql,
                                                             p_xq, fcos, fsin); // 1
    gemm_projk<<<dim3(256 / 128, NROWS / 128), 256, SM_BIG>>>(p_xh, p_xl, p_wkh, p_wkl,
                                                              p_xk, fcos, fsin);// 2
    transpose_k<<<(BSZ * NKV * HD * SEQ + 255) / 256, 256>>>(p_xk, p_xkT);      // 3
    scores2<<<dim3(SEQ / 16, NH, BSZ), 256>>>(p_xq, p_xkT, attn, p_ah, p_al);   // 4
    gemm_ws<<<dim3(DM / 256, SEQ), 256, SM_WS2>>>(p_ah, p_al, symbols, p_wsh, p_wsl); // 5
    gemm_wsv<<<dim3(SEQ / 128, 64), 256, SM_WSV>>>(p_wsh, p_wsl, p_wvh, p_wvl, p_oph, p_opl); // 6
    gemm_wo<<<dim3(DM / 128, NROWS / 128), 256, SM_BIG>>>(p_oph, p_opl, p_woh, p_wol, out);   // 7
}